// round 4
// baseline (speedup 1.0000x reference)
#include <cuda_runtime.h>
#include <math.h>

#define B 8
#define NS 25
#define NQ 75
#define WAY 5
#define C 512
#define HW 36
#define MID 6
#define NCLS 64
#define BJ (B*NQ)      // 600
#define BI (B*WAY)     // 40
#define LOGITS_N (BJ*NCLS*HW)   // 1382400

// ---------------- scratch ----------------
__device__ float g_protosT[BI*HW*C];   // [bi][x][c]
__device__ float g_inv1[BI*HW];
__device__ float g_f1nbar[BI*C];
__device__ float g_inv2[BJ*HW];
__device__ float g_f2nbar[BJ*C];
__device__ float g_w1q[BJ*MID*C];      // [(bj*6+ch)*512+c]
__device__ float g_w1p[BI*MID*C];      // [(bi*6+ch)*512+c]
__device__ float g_h1[BI*NQ*MID];      // [(bi*75+j)*6+ch]
__device__ float g_h2[BI*NQ*MID];
__device__ float g_bnscale[2*MID];
__device__ float g_bnshift[2*MID];
__device__ float g_att2[BJ*WAY*HW];    // [(bj*5+i)*36+y]

// ---------------- K1: prototypes ----------------
__global__ void k1_protos(const float* __restrict__ sup, const float* __restrict__ st) {
    int b = blockIdx.y;
    int idx = blockIdx.x * 256 + threadIdx.x;          // < 18432
    __shared__ float st_s[NS*WAY];
    if (threadIdx.x < NS*WAY) st_s[threadIdx.x] = st[b*NS*WAY + threadIdx.x];
    __syncthreads();
    int c = idx / HW, x = idx % HW;
    float acc[WAY]; float cnt[WAY];
#pragma unroll
    for (int i = 0; i < WAY; i++) { acc[i] = 0.f; cnt[i] = 0.f; }
    const float* sb = sup + (size_t)b*NS*C*HW + (size_t)c*HW + x;
    for (int n = 0; n < NS; n++) {
        float v = sb[(size_t)n*C*HW];
#pragma unroll
        for (int i = 0; i < WAY; i++) { float w = st_s[n*WAY+i]; acc[i] += w*v; cnt[i] += w; }
    }
#pragma unroll
    for (int i = 0; i < WAY; i++)
        g_protosT[((size_t)(b*WAY+i)*HW + x)*C + c] = acc[i] / cnt[i];
}

// ---------------- K1b: inv1 + f1nbar + W1p ----------------
__global__ void k1b_norms(const float* __restrict__ w1) {
    int bi = blockIdx.x;                                // 0..39
    __shared__ float inv1_s[HW];
    __shared__ float wi1[MID*HW];
    int t = threadIdx.x;                                // 512
    int w = t >> 5, lane = t & 31;
    const float* p = g_protosT + (size_t)bi*HW*C;
    for (int x = w; x < HW; x += 16) {
        float s0 = 0.f, s1 = 0.f;
        for (int c = lane; c < C; c += 64) {
            float v0 = p[x*C + c];      s0 += v0*v0;
            float v1 = p[x*C + c + 32]; s1 += v1*v1;
        }
        float s = s0 + s1;
#pragma unroll
        for (int o = 16; o; o >>= 1) s += __shfl_down_sync(0xffffffffu, s, o);
        if (lane == 0) {
            float inv = 1.f / fmaxf(sqrtf(s), 1e-12f);
            inv1_s[x] = inv;
            g_inv1[bi*HW + x] = inv;
        }
    }
    __syncthreads();
    if (t < MID*HW) wi1[t] = w1[t] * inv1_s[t % HW];
    __syncthreads();
    int c = t;
    float accb = 0.f, a0=0.f,a1=0.f,a2=0.f,a3=0.f,a4=0.f,a5=0.f;
#pragma unroll 4
    for (int x = 0; x < HW; x++) {
        float pv = p[x*C + c];
        accb += pv * inv1_s[x];
        a0 += pv*wi1[0*HW+x]; a1 += pv*wi1[1*HW+x]; a2 += pv*wi1[2*HW+x];
        a3 += pv*wi1[3*HW+x]; a4 += pv*wi1[4*HW+x]; a5 += pv*wi1[5*HW+x];
    }
    g_f1nbar[bi*C + c] = accb * (1.f/HW);
    float* wp = g_w1p + (size_t)bi*MID*C;
    wp[0*C+c]=a0; wp[1*C+c]=a1; wp[2*C+c]=a2; wp[3*C+c]=a3; wp[4*C+c]=a4; wp[5*C+c]=a5;
}

// ---------------- K2: inv2 + f2nbar + W1q (query staged in smem) ----------------
#define QPAD 37
__global__ void k2_qnorms(const float* __restrict__ query, const float* __restrict__ w1) {
    extern __shared__ float qs[];                       // [512][37]
    __shared__ float red[8*HW];
    __shared__ float inv2_s[HW];
    __shared__ float wi[MID*HW];
    int bj = blockIdx.x;
    const float* q = query + (size_t)bj*C*HW;
    int t = threadIdx.x;                                // 288
    for (int k = t; k < C*HW; k += 288) qs[(k/HW)*QPAD + k%HW] = q[k];
    __syncthreads();
    int y = t % HW, g = t / HW;                         // g < 8
    float ss = 0.f;
    for (int c = g; c < C; c += 8) { float v = qs[c*QPAD + y]; ss += v*v; }
    red[g*HW + y] = ss;
    __syncthreads();
    if (t < HW) {
        float s = 0.f;
#pragma unroll
        for (int gg = 0; gg < 8; gg++) s += red[gg*HW + t];
        float inv = 1.f / fmaxf(sqrtf(s), 1e-12f);
        inv2_s[t] = inv;
        g_inv2[bj*HW + t] = inv;
    }
    __syncthreads();
    if (t < MID*HW) wi[t] = w1[t] * inv2_s[t % HW];
    __syncthreads();
    float* wq = g_w1q + (size_t)bj*MID*C;
    for (int c = t; c < C; c += 288) {
        float accb=0.f, a0=0.f,a1=0.f,a2=0.f,a3=0.f,a4=0.f,a5=0.f;
#pragma unroll 4
        for (int yy = 0; yy < HW; yy++) {
            float qv = qs[c*QPAD + yy];
            accb += qv * inv2_s[yy];
            a0 += qv*wi[0*HW+yy]; a1 += qv*wi[1*HW+yy]; a2 += qv*wi[2*HW+yy];
            a3 += qv*wi[3*HW+yy]; a4 += qv*wi[4*HW+yy]; a5 += qv*wi[5*HW+yy];
        }
        g_f2nbar[bj*C + c] = accb * (1.f/HW);
        wq[0*C+c]=a0; wq[1*C+c]=a1; wq[2*C+c]=a2; wq[3*C+c]=a3; wq[4*C+c]=a4; wq[5*C+c]=a5;
    }
}

// ---------------- KC: h1/h2 (60 dot-512 per bj) ----------------
__global__ void kc_h(const float* __restrict__ b1) {
    int bj = blockIdx.x; int b = bj / NQ, j = bj % NQ;
    int t = threadIdx.x;                                // 256
    int w = t >> 5, lane = t & 31;
    for (int r = w; r < 2*WAY*MID; r += 8) {
        int path = r / (WAY*MID);
        int i = (r % (WAY*MID)) / MID, ch = r % MID;
        int bi = b*WAY + i;
        const float* va; const float* vb;
        if (path == 0) { va = g_f1nbar + (size_t)bi*C;           vb = g_w1q + ((size_t)bj*MID + ch)*C; }
        else           { va = g_w1p   + ((size_t)bi*MID + ch)*C; vb = g_f2nbar + (size_t)bj*C; }
        float s = 0.f;
        for (int c = lane; c < C; c += 32) s += va[c] * vb[c];
#pragma unroll
        for (int o = 16; o; o >>= 1) s += __shfl_down_sync(0xffffffffu, s, o);
        if (lane == 0) {
            float h = s + b1[ch];
            if (path == 0) g_h1[((size_t)bi*NQ + j)*MID + ch] = h;
            else           g_h2[((size_t)bi*NQ + j)*MID + ch] = h;
        }
    }
}

// ---------------- K4: deterministic BN stats ----------------
__global__ void k4_bn(const float* __restrict__ gamma, const float* __restrict__ beta) {
    int p = blockIdx.x / MID, ch = blockIdx.x % MID;
    const float* h = p ? g_h2 : g_h1;
    int t = threadIdx.x;                                // 256
    double s = 0.0, sq = 0.0;
    for (int n = t; n < BI*NQ; n += 256) {              // 3000 rows
        double v = (double)h[n*MID + ch];
        s += v; sq += v*v;
    }
    __shared__ double rs[256], rq[256];
    rs[t] = s; rq[t] = sq;
    __syncthreads();
    for (int o = 128; o; o >>= 1) {
        if (t < o) { rs[t] += rs[t+o]; rq[t] += rq[t+o]; }
        __syncthreads();
    }
    if (t == 0) {
        double mu  = rs[0] / 3000.0;
        double var = rq[0] / 3000.0 - mu*mu;
        float sd = sqrtf((float)var + 1e-5f);
        float sc = gamma[ch] / sd;
        g_bnscale[p*MID + ch] = sc;
        g_bnshift[p*MID + ch] = beta[ch] - (float)mu * sc;
    }
}

// ---------------- K5: per-(b,i) attention, j tiled by 5 ----------------
#define JT 5
__global__ void k5_attn(const float* __restrict__ query,
                        const float* __restrict__ w2, const float* __restrict__ b2,
                        float* __restrict__ out_cls) {
    extern __shared__ __align__(16) float sm[];
    float* ps     = sm;                  // [36][512]
    float* qs     = ps + HW*C;           // [512][37]
    float* v1_s   = qs + C*QPAD;         // 512
    float* u_s    = v1_s + C;            // 512
    float* pp_s   = u_s + C;             // 512
    float* inv1_s = pp_s + C;            // 36
    float* inv2_s = inv1_s + HW;         // 36
    float* w2_s   = inv2_s + HW;         // 216
    float* b2_s   = w2_s + MID*HW;       // 36
    float* scl    = b2_s + HW;           // 12
    float* shf    = scl + 2*MID;         // 12
    float* attp2_s= shf + 2*MID;         // 36
    float* wv     = attp2_s + HW;        // 36
    float* coef2  = wv + HW;             // 36
    float* s_s    = coef2 + HW;          // 36
    float* att1_s = s_s + HW;            // 36
    float* red    = att1_s + HW;         // 8
    float* pninv_s= red + 8;             // 1

    int bi = blockIdx.y; int b = bi / WAY, i = bi % WAY;
    int j0 = blockIdx.x * JT;
    int t = threadIdx.x;                                // 256
    int w = t >> 5, lane = t & 31;

    // load protos tile once
    {
        const float4* pg = (const float4*)(g_protosT + (size_t)bi*HW*C);
        float4* pd = (float4*)ps;
        for (int k = t; k < HW*C/4; k += 256) pd[k] = pg[k];
    }
    if (t < HW) inv1_s[t] = g_inv1[bi*HW + t];
    if (t < MID*HW) w2_s[t] = w2[t];
    if (t < HW) b2_s[t] = b2[t];
    if (t < 2*MID) { scl[t] = g_bnscale[t]; shf[t] = g_bnshift[t]; }
    __syncthreads();

    for (int jj = 0; jj < JT; jj++) {
        int j = j0 + jj, bj = b*NQ + j;
        const float* q = query + (size_t)bj*C*HW;
        for (int k = t; k < C*HW; k += 256) qs[(k/HW)*QPAD + k%HW] = q[k];
        if (t < HW) {
            float iv2 = g_inv2[bj*HW + t];
            inv2_s[t] = iv2;
            const float* h1p = g_h1 + ((size_t)bi*NQ + j)*MID;
            const float* h2p = g_h2 + ((size_t)bi*NQ + j)*MID;
            float a1 = b2_s[t], a2 = b2_s[t];
#pragma unroll
            for (int ch = 0; ch < MID; ch++) {
                float r1 = fmaxf(h1p[ch]*scl[ch]     + shf[ch],     0.f);
                float r2 = fmaxf(h2p[ch]*scl[MID+ch] + shf[MID+ch], 0.f);
                a1 += w2_s[t*MID + ch] * r1;
                a2 += w2_s[t*MID + ch] * r2;
            }
            attp2_s[t] = a2;
            wv[t]    = iv2 * a1 * (1.f/HW);
            coef2[t] = inv1_s[t] * a2 * (1.f/HW);
        }
        __syncthreads();

        // pass1: v1[c], u[c]
        for (int c = t; c < C; c += 256) {
            float v = 0.f, uu = 0.f;
#pragma unroll 4
            for (int y = 0; y < HW; y++) v += qs[c*QPAD + y] * wv[y];
#pragma unroll 4
            for (int x = 0; x < HW; x++) uu += ps[x*C + c] * coef2[x];
            v1_s[c] = v; u_s[c] = uu;
        }
        __syncthreads();

        // s1[x] = inv1[x] * p[x,:].v1
        for (int x = w; x < HW; x += 8) {
            float s = 0.f;
            for (int c = lane; c < C; c += 32) s += ps[x*C + c] * v1_s[c];
#pragma unroll
            for (int o = 16; o; o >>= 1) s += __shfl_down_sync(0xffffffffu, s, o);
            if (lane == 0) s_s[x] = s * inv1_s[x];
        }
        __syncthreads();

        // softmax over x (+1) by warp 0
        if (t < 32) {
            float v0 = s_s[t];
            float v1v = (t + 32 < HW) ? s_s[t + 32] : -1e30f;
            float mx = fmaxf(v0, v1v);
#pragma unroll
            for (int o = 16; o; o >>= 1) mx = fmaxf(mx, __shfl_xor_sync(0xffffffffu, mx, o));
            float e0 = expf((v0 - mx) * 40.f);
            float e1 = (t + 32 < HW) ? expf((v1v - mx) * 40.f) : 0.f;
            float sum = e0 + e1;
#pragma unroll
            for (int o = 16; o; o >>= 1) sum += __shfl_xor_sync(0xffffffffu, sum, o);
            float inv = 1.f / sum;
            att1_s[t] = e0*inv + 1.f;
            if (t + 32 < HW) att1_s[t + 32] = e1*inv + 1.f;
        }
        __syncthreads();

        // pass2: pp[c] + norm
        float sq = 0.f;
        for (int c = t; c < C; c += 256) {
            float a = 0.f;
#pragma unroll 4
            for (int x = 0; x < HW; x++) a += ps[x*C + c] * att1_s[x];
            a *= (1.f/HW);
            pp_s[c] = a;
            sq += a*a;
        }
#pragma unroll
        for (int o = 16; o; o >>= 1) sq += __shfl_down_sync(0xffffffffu, sq, o);
        if (lane == 0) red[w] = sq;
        __syncthreads();
        if (t == 0) {
            float s = 0.f;
#pragma unroll
            for (int g = 0; g < 8; g++) s += red[g];
            pninv_s[0] = 1.f / fmaxf(sqrtf(s), 1e-12f);
        }
        __syncthreads();

        // pass3: cls[y] and s2[y]
        float pninv = pninv_s[0];
        for (int y = w; y < HW; y += 8) {
            float d1 = 0.f, d2 = 0.f;
            for (int c = lane; c < C; c += 32) {
                float qv = qs[c*QPAD + y];
                d1 += qv * pp_s[c];
                d2 += qv * u_s[c];
            }
#pragma unroll
            for (int o = 16; o; o >>= 1) {
                d1 += __shfl_down_sync(0xffffffffu, d1, o);
                d2 += __shfl_down_sync(0xffffffffu, d2, o);
            }
            if (lane == 0) {
                out_cls[((size_t)bj*WAY + i)*HW + y] = 7.f * pninv * inv2_s[y] * d1;
                s_s[y] = inv2_s[y] * d2;
            }
        }
        __syncthreads();

        // softmax over y (+1) -> g_att2, warp 0
        if (t < 32) {
            float v0 = s_s[t];
            float v1v = (t + 32 < HW) ? s_s[t + 32] : -1e30f;
            float mx = fmaxf(v0, v1v);
#pragma unroll
            for (int o = 16; o; o >>= 1) mx = fmaxf(mx, __shfl_xor_sync(0xffffffffu, mx, o));
            float e0 = expf((v0 - mx) * 40.f);
            float e1 = (t + 32 < HW) ? expf((v1v - mx) * 40.f) : 0.f;
            float sum = e0 + e1;
#pragma unroll
            for (int o = 16; o; o >>= 1) sum += __shfl_xor_sync(0xffffffffu, sum, o);
            float inv = 1.f / sum;
            float* a2p = g_att2 + ((size_t)bj*WAY + i)*HW;
            a2p[t] = e0*inv + 1.f;
            if (t + 32 < HW) a2p[t + 32] = e1*inv + 1.f;
        }
        __syncthreads();
    }
}
#define K5_SMEM ((HW*C + C*QPAD + 3*C + 5*HW + MID*HW + HW + 4*MID + 4*HW + 9)*4 + 64)

// ---------------- K6: logits ----------------
__global__ void k6_logits(const float* __restrict__ query, const float* __restrict__ qt,
                          const float* __restrict__ clsw, const float* __restrict__ clsb,
                          float* __restrict__ out_logits) {
    __shared__ __align__(16) float qs[64*40];
    __shared__ __align__(16) float ws[64*68];
    __shared__ float asel[HW];
    __shared__ float cb[NCLS];
    __shared__ float qt_s[WAY];
    int bj = blockIdx.x;
    int t = threadIdx.x;                                // 144
    if (t < WAY) qt_s[t] = qt[bj*WAY + t];
    if (t < NCLS) cb[t] = clsb[t];
    __syncthreads();
    if (t < HW) {
        float a = 0.f;
#pragma unroll
        for (int i = 0; i < WAY; i++)
            a += qt_s[i] * g_att2[((size_t)bj*WAY + i)*HW + t];
        asel[t] = a;
    }
    int og = t & 15, yg = t >> 4;                       // 16 x 9
    int o0 = og*4, y0 = yg*4;
    float acc[16];
#pragma unroll
    for (int k = 0; k < 16; k++) acc[k] = 0.f;
    const float* q = query + (size_t)bj*C*HW;
    for (int c0 = 0; c0 < C; c0 += 64) {
        __syncthreads();
        for (int k = t; k < 64*HW; k += 144) {
            int c = k / HW, y = k % HW;
            qs[c*40 + y] = q[(c0 + c)*HW + y];
        }
        for (int k = t; k < 64*64; k += 144) {
            int c = k & 63, o = k >> 6;
            ws[c*68 + o] = clsw[o*C + c0 + c];
        }
        __syncthreads();
#pragma unroll 4
        for (int cc = 0; cc < 64; cc++) {
            float4 wv = *(const float4*)&ws[cc*68 + o0];
            float4 qv = *(const float4*)&qs[cc*40 + y0];
            acc[0]  += wv.x*qv.x; acc[1]  += wv.x*qv.y; acc[2]  += wv.x*qv.z; acc[3]  += wv.x*qv.w;
            acc[4]  += wv.y*qv.x; acc[5]  += wv.y*qv.y; acc[6]  += wv.y*qv.z; acc[7]  += wv.y*qv.w;
            acc[8]  += wv.z*qv.x; acc[9]  += wv.z*qv.y; acc[10] += wv.z*qv.z; acc[11] += wv.z*qv.w;
            acc[12] += wv.w*qv.x; acc[13] += wv.w*qv.y; acc[14] += wv.w*qv.z; acc[15] += wv.w*qv.w;
        }
    }
    float* op = out_logits + (size_t)bj*NCLS*HW;
#pragma unroll
    for (int oo = 0; oo < 4; oo++)
#pragma unroll
        for (int yy = 0; yy < 4; yy++)
            op[(o0+oo)*HW + y0 + yy] = asel[y0+yy]*acc[oo*4+yy] + cb[o0+oo];
}

// ---------------- launch ----------------
extern "C" void kernel_launch(void* const* d_in, const int* in_sizes, int n_in,
                              void* d_out, int out_size) {
    const float* sup   = (const float*)d_in[0];
    const float* query = (const float*)d_in[1];
    const float* st    = (const float*)d_in[2];
    const float* qt    = (const float*)d_in[3];
    const float* w1    = (const float*)d_in[4];
    const float* b1    = (const float*)d_in[5];
    const float* gamma = (const float*)d_in[6];
    const float* beta  = (const float*)d_in[7];
    const float* w2    = (const float*)d_in[8];
    const float* b2    = (const float*)d_in[9];
    const float* clsw  = (const float*)d_in[10];
    const float* clsb  = (const float*)d_in[11];
    float* out = (float*)d_out;

    cudaFuncSetAttribute(k5_attn, cudaFuncAttributeMaxDynamicSharedMemorySize, K5_SMEM);
    cudaFuncSetAttribute(k2_qnorms, cudaFuncAttributeMaxDynamicSharedMemorySize, C*QPAD*4);

    k1_protos<<<dim3(72, B), 256>>>(sup, st);
    k1b_norms<<<BI, 512>>>(w1);
    k2_qnorms<<<BJ, 288, C*QPAD*4>>>(query, w1);
    kc_h<<<BJ, 256>>>(b1);
    k4_bn<<<2*MID, 256>>>(gamma, beta);
    k5_attn<<<dim3(NQ/JT, BI), 256, K5_SMEM>>>(query, w2, b2, out + LOGITS_N);
    k6_logits<<<BJ, 144>>>(query, qt, clsw, clsb, out);
}

// round 5
// speedup vs baseline: 1.5931x; 1.5931x over previous
#include <cuda_runtime.h>
#include <math.h>

#define B 8
#define NS 25
#define NQ 75
#define WAY 5
#define C 512
#define HW 36
#define MID 6
#define NCLS 64
#define BJ (B*NQ)      // 600
#define BI (B*WAY)     // 40
#define LOGITS_N (BJ*NCLS*HW)   // 1382400
#define QPAD 37

// ---------------- scratch ----------------
__device__ float g_protosT[BI*HW*C];   // [bi][x][c]
__device__ float g_inv1[BI*HW];
__device__ float g_f1nbar[BI*C];
__device__ float g_inv2[BJ*HW];
__device__ float g_f2nbar[BJ*C];
__device__ float g_w1q[BJ*MID*C];      // [(bj*6+ch)*512+c]
__device__ float g_w1p[BI*MID*C];      // [(bi*6+ch)*512+c]
__device__ float g_h1[BI*NQ*MID];      // [(bi*75+j)*6+ch]
__device__ float g_h2[BI*NQ*MID];
__device__ float g_bnscale[2*MID];
__device__ float g_bnshift[2*MID];
__device__ float g_att2[BJ*WAY*HW];    // [(bj*5+i)*36+y]

// ---------------- K1: prototypes ----------------
__global__ void k1_protos(const float* __restrict__ sup, const float* __restrict__ st) {
    int b = blockIdx.y;
    int idx = blockIdx.x * 256 + threadIdx.x;          // < 18432
    __shared__ float st_s[NS*WAY];
    if (threadIdx.x < NS*WAY) st_s[threadIdx.x] = st[b*NS*WAY + threadIdx.x];
    __syncthreads();
    int c = idx / HW, x = idx % HW;
    float acc[WAY]; float cnt[WAY];
#pragma unroll
    for (int i = 0; i < WAY; i++) { acc[i] = 0.f; cnt[i] = 0.f; }
    const float* sb = sup + (size_t)b*NS*C*HW + (size_t)c*HW + x;
    for (int n = 0; n < NS; n++) {
        float v = sb[(size_t)n*C*HW];
#pragma unroll
        for (int i = 0; i < WAY; i++) { float w = st_s[n*WAY+i]; acc[i] += w*v; cnt[i] += w; }
    }
#pragma unroll
    for (int i = 0; i < WAY; i++)
        g_protosT[((size_t)(b*WAY+i)*HW + x)*C + c] = acc[i] / cnt[i];
}

// ---------------- K1b: inv1 + f1nbar + W1p ----------------
__global__ void k1b_norms(const float* __restrict__ w1) {
    int bi = blockIdx.x;                                // 0..39
    __shared__ float inv1_s[HW];
    __shared__ float wi1[MID*HW];
    int t = threadIdx.x;                                // 512
    int w = t >> 5, lane = t & 31;
    const float* p = g_protosT + (size_t)bi*HW*C;
    for (int x = w; x < HW; x += 16) {
        float s0 = 0.f, s1 = 0.f;
        for (int c = lane; c < C; c += 64) {
            float v0 = p[x*C + c];      s0 += v0*v0;
            float v1 = p[x*C + c + 32]; s1 += v1*v1;
        }
        float s = s0 + s1;
#pragma unroll
        for (int o = 16; o; o >>= 1) s += __shfl_down_sync(0xffffffffu, s, o);
        if (lane == 0) {
            float inv = 1.f / fmaxf(sqrtf(s), 1e-12f);
            inv1_s[x] = inv;
            g_inv1[bi*HW + x] = inv;
        }
    }
    __syncthreads();
    if (t < MID*HW) wi1[t] = w1[t] * inv1_s[t % HW];
    __syncthreads();
    int c = t;
    float accb = 0.f, a0=0.f,a1=0.f,a2=0.f,a3=0.f,a4=0.f,a5=0.f;
#pragma unroll 4
    for (int x = 0; x < HW; x++) {
        float pv = p[x*C + c];
        accb += pv * inv1_s[x];
        a0 += pv*wi1[0*HW+x]; a1 += pv*wi1[1*HW+x]; a2 += pv*wi1[2*HW+x];
        a3 += pv*wi1[3*HW+x]; a4 += pv*wi1[4*HW+x]; a5 += pv*wi1[5*HW+x];
    }
    g_f1nbar[bi*C + c] = accb * (1.f/HW);
    float* wp = g_w1p + (size_t)bi*MID*C;
    wp[0*C+c]=a0; wp[1*C+c]=a1; wp[2*C+c]=a2; wp[3*C+c]=a3; wp[4*C+c]=a4; wp[5*C+c]=a5;
}

// ---------------- K2: inv2 + f2nbar + W1q ----------------
__global__ void k2_qnorms(const float* __restrict__ query, const float* __restrict__ w1) {
    extern __shared__ float qs[];                       // [512][37]
    __shared__ float red[8*HW];
    __shared__ float inv2_s[HW];
    __shared__ float wi[MID*HW];
    int bj = blockIdx.x;
    const float* q = query + (size_t)bj*C*HW;
    int t = threadIdx.x;                                // 512
    for (int k = t; k < C*HW; k += 512) qs[(k/HW)*QPAD + k%HW] = q[k];
    __syncthreads();
    if (t < 8*HW) {
        int y = t % HW, g = t / HW;
        float ss = 0.f;
        for (int c = g; c < C; c += 8) { float v = qs[c*QPAD + y]; ss += v*v; }
        red[g*HW + y] = ss;
    }
    __syncthreads();
    if (t < HW) {
        float s = 0.f;
#pragma unroll
        for (int gg = 0; gg < 8; gg++) s += red[gg*HW + t];
        float inv = 1.f / fmaxf(sqrtf(s), 1e-12f);
        inv2_s[t] = inv;
        g_inv2[bj*HW + t] = inv;
    }
    __syncthreads();
    if (t < MID*HW) wi[t] = w1[t] * inv2_s[t % HW];
    __syncthreads();
    float* wq = g_w1q + (size_t)bj*MID*C;
    int c = t;
    float accb=0.f, a0=0.f,a1=0.f,a2=0.f,a3=0.f,a4=0.f,a5=0.f;
#pragma unroll 4
    for (int yy = 0; yy < HW; yy++) {
        float qv = qs[c*QPAD + yy];
        accb += qv * inv2_s[yy];
        a0 += qv*wi[0*HW+yy]; a1 += qv*wi[1*HW+yy]; a2 += qv*wi[2*HW+yy];
        a3 += qv*wi[3*HW+yy]; a4 += qv*wi[4*HW+yy]; a5 += qv*wi[5*HW+yy];
    }
    g_f2nbar[bj*C + c] = accb * (1.f/HW);
    wq[0*C+c]=a0; wq[1*C+c]=a1; wq[2*C+c]=a2; wq[3*C+c]=a3; wq[4*C+c]=a4; wq[5*C+c]=a5;
}

// ---------------- KC: h1/h2, tiled over j (grid (B, NQ/KCJT)) ----------------
#define KCJT 5
__global__ void kc_h(const float* __restrict__ b1) {
    extern __shared__ float kcsm[];
    float* fb  = kcsm;                 // [5][512]
    float* wp  = fb + WAY*C;           // [30][512]
    float* f2  = wp + WAY*MID*C;       // [KCJT][512]
    float* b1s = f2 + KCJT*C;          // 6
    int b = blockIdx.x, j0 = blockIdx.y * KCJT;
    int t = threadIdx.x;               // 256
    for (int k = t; k < WAY*C; k += 256) fb[k] = g_f1nbar[b*WAY*C + k];
    for (int k = t; k < WAY*MID*C; k += 256) wp[k] = g_w1p[(size_t)b*WAY*MID*C + k];
    for (int k = t; k < KCJT*C; k += 256)
        f2[k] = g_f2nbar[(size_t)(b*NQ + j0 + k/C)*C + (k % C)];
    if (t < MID) b1s[t] = b1[t];
    __syncthreads();
    int w = t >> 5, lane = t & 31;
    for (int r = w; r < KCJT*2*WAY*MID; r += 8) {   // 300 dots
        int jj = r / (2*WAY*MID);
        int rr = r % (2*WAY*MID);
        int path = rr / (WAY*MID);
        int rem = rr % (WAY*MID);
        int i = rem / MID, ch = rem % MID;
        int j = j0 + jj, bj = b*NQ + j, bi = b*WAY + i;
        float s = 0.f;
        if (path == 0) {
            const float* wqv = g_w1q + ((size_t)bj*MID + ch)*C;
            const float* fv = fb + i*C;
            for (int c = lane; c < C; c += 32) s += fv[c] * wqv[c];
        } else {
            const float* wpv = wp + (i*MID + ch)*C;
            const float* fv = f2 + jj*C;
            for (int c = lane; c < C; c += 32) s += wpv[c] * fv[c];
        }
#pragma unroll
        for (int o = 16; o; o >>= 1) s += __shfl_down_sync(0xffffffffu, s, o);
        if (lane == 0) {
            float h = s + b1s[ch];
            if (path == 0) g_h1[((size_t)bi*NQ + j)*MID + ch] = h;
            else           g_h2[((size_t)bi*NQ + j)*MID + ch] = h;
        }
    }
}
#define KC_SMEM ((WAY*C + WAY*MID*C + KCJT*C + 8)*4)

// ---------------- K4: deterministic BN stats ----------------
__global__ void k4_bn(const float* __restrict__ gamma, const float* __restrict__ beta) {
    int p = blockIdx.x / MID, ch = blockIdx.x % MID;
    const float* h = p ? g_h2 : g_h1;
    int t = threadIdx.x;                                // 256
    double s = 0.0, sq = 0.0;
    for (int n = t; n < BI*NQ; n += 256) {
        double v = (double)h[n*MID + ch];
        s += v; sq += v*v;
    }
    __shared__ double rs[256], rq[256];
    rs[t] = s; rq[t] = sq;
    __syncthreads();
    for (int o = 128; o; o >>= 1) {
        if (t < o) { rs[t] += rs[t+o]; rq[t] += rq[t+o]; }
        __syncthreads();
    }
    if (t == 0) {
        double mu  = rs[0] / 3000.0;
        double var = rq[0] / 3000.0 - mu*mu;
        float sd = sqrtf((float)var + 1e-5f);
        float sc = gamma[ch] / sd;
        g_bnscale[p*MID + ch] = sc;
        g_bnshift[p*MID + ch] = beta[ch] - (float)mu * sc;
    }
}

// ---------------- K5: per-(b,j), all i batched, 512 threads ----------------
__global__ void k5_attn(const float* __restrict__ query,
                        const float* __restrict__ w2, const float* __restrict__ b2,
                        float* __restrict__ out_cls) {
    extern __shared__ __align__(16) float sm[];
    float* qs     = sm;                  // [512][37]
    float* vu     = qs + C*QPAD;         // [5][512]: v1, later u
    float* pp     = vu + WAY*C;          // [5][512]
    float* inv1_s = pp + WAY*C;          // 180
    float* inv2_s = inv1_s + WAY*HW;     // 36
    float* w2_s   = inv2_s + HW;         // 216
    float* b2_s   = w2_s + MID*HW;       // 36
    float* scl    = b2_s + HW;           // 12
    float* shf    = scl + 2*MID;         // 12
    float* wv     = shf + 2*MID;         // 180
    float* coef2  = wv + WAY*HW;         // 180
    float* s_s    = coef2 + WAY*HW;      // 180
    float* att_s  = s_s + WAY*HW;        // 180
    float* red    = att_s + WAY*HW;      // 80
    float* pninv  = red + 80;            // 8

    int bj = blockIdx.x; int b = bj / NQ, j = bj % NQ;
    int t = threadIdx.x;                                // 512
    int w = t >> 5, lane = t & 31;
    const float* q = query + (size_t)bj*C*HW;
    const float* pbase = g_protosT + (size_t)b*WAY*HW*C;

    for (int k = t; k < C*HW; k += 512) qs[(k/HW)*QPAD + k%HW] = q[k];
    if (t < WAY*HW) inv1_s[t] = g_inv1[b*WAY*HW + t];
    if (t < HW) inv2_s[t] = g_inv2[bj*HW + t];
    if (t < MID*HW) w2_s[t] = w2[t];
    if (t < HW) b2_s[t] = b2[t];
    if (t < 2*MID) { scl[t] = g_bnscale[t]; shf[t] = g_bnshift[t]; }
    __syncthreads();

    // prologue: attention pre-activations -> wv (path1 weights), coef2 (path2)
    if (t < WAY*HW) {
        int i = t / HW, y = t % HW;
        const float* h1p = g_h1 + ((size_t)(b*WAY+i)*NQ + j)*MID;
        const float* h2p = g_h2 + ((size_t)(b*WAY+i)*NQ + j)*MID;
        float a1 = b2_s[y], a2 = b2_s[y];
#pragma unroll
        for (int ch = 0; ch < MID; ch++) {
            float r1 = fmaxf(h1p[ch]*scl[ch]     + shf[ch],     0.f);
            float r2 = fmaxf(h2p[ch]*scl[MID+ch] + shf[MID+ch], 0.f);
            a1 += w2_s[y*MID + ch] * r1;
            a2 += w2_s[y*MID + ch] * r2;
        }
        wv[t]    = inv2_s[y] * a1 * (1.f/HW);
        coef2[t] = inv1_s[t] * a2 * (1.f/HW);
    }
    __syncthreads();

    // pass1: v1[i][c] from query (one c per thread)
    {
        int c = t;
        float a0=0.f,a1=0.f,a2=0.f,a3=0.f,a4=0.f;
#pragma unroll 4
        for (int y = 0; y < HW; y++) {
            float qv = qs[c*QPAD + y];
            a0 += qv*wv[0*HW+y]; a1 += qv*wv[1*HW+y]; a2 += qv*wv[2*HW+y];
            a3 += qv*wv[3*HW+y]; a4 += qv*wv[4*HW+y];
        }
        vu[0*C+c]=a0; vu[1*C+c]=a1; vu[2*C+c]=a2; vu[3*C+c]=a3; vu[4*C+c]=a4;
    }
    __syncthreads();

    // pass2: s1[i][x] = inv1 * p[i,x,:].v1  (warp per row, 16 warps)
    for (int r = w; r < WAY*HW; r += 16) {
        int i = r / HW, x = r % HW;
        const float* p = pbase + (size_t)(i*HW + x)*C;
        const float* v = vu + i*C;
        float s = 0.f;
        for (int c = lane; c < C; c += 32) s += p[c]*v[c];
#pragma unroll
        for (int o = 16; o; o >>= 1) s += __shfl_down_sync(0xffffffffu, s, o);
        if (lane == 0) s_s[r] = s * inv1_s[r];
    }
    __syncthreads();

    // softmax1 over x (+1): warp i handles row i
    if (w < WAY) {
        int i = w;
        float v0 = s_s[i*HW + lane];
        float v1v = (lane < HW-32) ? s_s[i*HW + 32 + lane] : -1e30f;
        float mx = fmaxf(v0, v1v);
#pragma unroll
        for (int o = 16; o; o >>= 1) mx = fmaxf(mx, __shfl_xor_sync(0xffffffffu, mx, o));
        float e0 = expf((v0 - mx) * 40.f);
        float e1 = (lane < HW-32) ? expf((v1v - mx) * 40.f) : 0.f;
        float sum = e0 + e1;
#pragma unroll
        for (int o = 16; o; o >>= 1) sum += __shfl_xor_sync(0xffffffffu, sum, o);
        float inv = 1.f / sum;
        att_s[i*HW + lane] = e0*inv + 1.f;
        if (lane < HW-32) att_s[i*HW + 32 + lane] = e1*inv + 1.f;
    }
    __syncthreads();

    // pass3: pp[i][c] (att1-pooled protos) and u[i][c] (coef2-pooled), + ||pp|| partials
    {
        int c = t;
        float sq[WAY];
#pragma unroll
        for (int i = 0; i < WAY; i++) {
            const float* p = pbase + (size_t)i*HW*C + c;
            float ap = 0.f, au = 0.f;
#pragma unroll 4
            for (int x = 0; x < HW; x++) {
                float pv = p[(size_t)x*C];
                ap += pv * att_s[i*HW + x];
                au += pv * coef2[i*HW + x];
            }
            ap *= (1.f/HW);
            pp[i*C + c] = ap;
            vu[i*C + c] = au;          // overwrite dead v1
            sq[i] = ap*ap;
        }
#pragma unroll
        for (int i = 0; i < WAY; i++) {
            float s = sq[i];
#pragma unroll
            for (int o = 16; o; o >>= 1) s += __shfl_down_sync(0xffffffffu, s, o);
            if (lane == 0) red[i*16 + w] = s;
        }
    }
    __syncthreads();
    if (t < WAY) {
        float s = 0.f;
#pragma unroll
        for (int g = 0; g < 16; g++) s += red[t*16 + g];
        pninv[t] = 1.f / fmaxf(sqrtf(s), 1e-12f);
    }
    __syncthreads();

    // pass4: cls_scores[i][y] and s2[i][y]  (warp per row)
    for (int r = w; r < WAY*HW; r += 16) {
        int i = r / HW, y = r % HW;
        float d1 = 0.f, d2 = 0.f;
        for (int c = lane; c < C; c += 32) {
            float qv = qs[c*QPAD + y];
            d1 += qv * pp[i*C + c];
            d2 += qv * vu[i*C + c];
        }
#pragma unroll
        for (int o = 16; o; o >>= 1) {
            d1 += __shfl_down_sync(0xffffffffu, d1, o);
            d2 += __shfl_down_sync(0xffffffffu, d2, o);
        }
        if (lane == 0) {
            out_cls[((size_t)bj*WAY + i)*HW + y] = 7.f * pninv[i] * inv2_s[y] * d1;
            s_s[r] = inv2_s[y] * d2;
        }
    }
    __syncthreads();

    // softmax2 over y (+1) -> g_att2
    if (w < WAY) {
        int i = w;
        float v0 = s_s[i*HW + lane];
        float v1v = (lane < HW-32) ? s_s[i*HW + 32 + lane] : -1e30f;
        float mx = fmaxf(v0, v1v);
#pragma unroll
        for (int o = 16; o; o >>= 1) mx = fmaxf(mx, __shfl_xor_sync(0xffffffffu, mx, o));
        float e0 = expf((v0 - mx) * 40.f);
        float e1 = (lane < HW-32) ? expf((v1v - mx) * 40.f) : 0.f;
        float sum = e0 + e1;
#pragma unroll
        for (int o = 16; o; o >>= 1) sum += __shfl_xor_sync(0xffffffffu, sum, o);
        float inv = 1.f / sum;
        float* a2p = g_att2 + ((size_t)bj*WAY + i)*HW;
        a2p[lane] = e0*inv + 1.f;
        if (lane < HW-32) a2p[32 + lane] = e1*inv + 1.f;
    }
}
#define K5_SMEM ((C*QPAD + 2*WAY*C + 6*WAY*HW + 2*HW + MID*HW + 4*MID + 88)*4 + 64)

// ---------------- K6: logits ----------------
__global__ void k6_logits(const float* __restrict__ query, const float* __restrict__ qt,
                          const float* __restrict__ clsw, const float* __restrict__ clsb,
                          float* __restrict__ out_logits) {
    __shared__ __align__(16) float qs[64*40];
    __shared__ __align__(16) float ws[64*68];
    __shared__ float asel[HW];
    __shared__ float cb[NCLS];
    __shared__ float qt_s[WAY];
    int bj = blockIdx.x;
    int t = threadIdx.x;                                // 144
    if (t < WAY) qt_s[t] = qt[bj*WAY + t];
    if (t < NCLS) cb[t] = clsb[t];
    __syncthreads();
    if (t < HW) {
        float a = 0.f;
#pragma unroll
        for (int i = 0; i < WAY; i++)
            a += qt_s[i] * g_att2[((size_t)bj*WAY + i)*HW + t];
        asel[t] = a;
    }
    int og = t & 15, yg = t >> 4;                       // 16 x 9
    int o0 = og*4, y0 = yg*4;
    float acc[16];
#pragma unroll
    for (int k = 0; k < 16; k++) acc[k] = 0.f;
    const float* q = query + (size_t)bj*C*HW;
    for (int c0 = 0; c0 < C; c0 += 64) {
        __syncthreads();
        for (int k = t; k < 64*HW; k += 144) {
            int c = k / HW, y = k % HW;
            qs[c*40 + y] = q[(c0 + c)*HW + y];
        }
        for (int k = t; k < 64*64; k += 144) {
            int c = k & 63, o = k >> 6;
            ws[c*68 + o] = clsw[o*C + c0 + c];
        }
        __syncthreads();
#pragma unroll 4
        for (int cc = 0; cc < 64; cc++) {
            float4 wvv = *(const float4*)&ws[cc*68 + o0];
            float4 qv = *(const float4*)&qs[cc*40 + y0];
            acc[0]  += wvv.x*qv.x; acc[1]  += wvv.x*qv.y; acc[2]  += wvv.x*qv.z; acc[3]  += wvv.x*qv.w;
            acc[4]  += wvv.y*qv.x; acc[5]  += wvv.y*qv.y; acc[6]  += wvv.y*qv.z; acc[7]  += wvv.y*qv.w;
            acc[8]  += wvv.z*qv.x; acc[9]  += wvv.z*qv.y; acc[10] += wvv.z*qv.z; acc[11] += wvv.z*qv.w;
            acc[12] += wvv.w*qv.x; acc[13] += wvv.w*qv.y; acc[14] += wvv.w*qv.z; acc[15] += wvv.w*qv.w;
        }
    }
    float* op = out_logits + (size_t)bj*NCLS*HW;
#pragma unroll
    for (int oo = 0; oo < 4; oo++)
#pragma unroll
        for (int yy = 0; yy < 4; yy++)
            op[(o0+oo)*HW + y0 + yy] = asel[y0+yy]*acc[oo*4+yy] + cb[o0+oo];
}

// ---------------- launch ----------------
extern "C" void kernel_launch(void* const* d_in, const int* in_sizes, int n_in,
                              void* d_out, int out_size) {
    const float* sup   = (const float*)d_in[0];
    const float* query = (const float*)d_in[1];
    const float* st    = (const float*)d_in[2];
    const float* qt    = (const float*)d_in[3];
    const float* w1    = (const float*)d_in[4];
    const float* b1    = (const float*)d_in[5];
    const float* gamma = (const float*)d_in[6];
    const float* beta  = (const float*)d_in[7];
    const float* w2    = (const float*)d_in[8];
    const float* b2    = (const float*)d_in[9];
    const float* clsw  = (const float*)d_in[10];
    const float* clsb  = (const float*)d_in[11];
    float* out = (float*)d_out;

    cudaFuncSetAttribute(k5_attn, cudaFuncAttributeMaxDynamicSharedMemorySize, K5_SMEM);
    cudaFuncSetAttribute(k2_qnorms, cudaFuncAttributeMaxDynamicSharedMemorySize, C*QPAD*4);
    cudaFuncSetAttribute(kc_h, cudaFuncAttributeMaxDynamicSharedMemorySize, KC_SMEM);

    k1_protos<<<dim3(72, B), 256>>>(sup, st);
    k1b_norms<<<BI, 512>>>(w1);
    k2_qnorms<<<BJ, 512, C*QPAD*4>>>(query, w1);
    kc_h<<<dim3(B, NQ/KCJT), 256, KC_SMEM>>>(b1);
    k4_bn<<<2*MID, 256>>>(gamma, beta);
    k5_attn<<<BJ, 512, K5_SMEM>>>(query, w2, b2, out + LOGITS_N);
    k6_logits<<<BJ, 144>>>(query, qt, clsw, clsb, out);
}

// round 8
// speedup vs baseline: 1.7288x; 1.0851x over previous
#include <cuda_runtime.h>
#include <math.h>

#define B 8
#define NS 25
#define NQ 75
#define WAY 5
#define C 512
#define HW 36
#define MID 6
#define NCLS 64
#define BJ (B*NQ)      // 600
#define BI (B*WAY)     // 40
#define LOGITS_N (BJ*NCLS*HW)   // 1382400
#define QPAD 37

// ---------------- scratch ----------------
__device__ float g_protosT[BI*HW*C];   // [bi][x][c]
__device__ float g_inv1[BI*HW];
__device__ float g_f1nbar[BI*C];
__device__ float g_inv2[BJ*HW];
__device__ float g_f2nbar[BJ*C];
__device__ float g_w1q[BJ*MID*C];      // [(bj*6+ch)*512+c]
__device__ float g_w1p[BI*MID*C];      // [(bi*6+ch)*512+c]
__device__ float g_h1[BI*NQ*MID];      // [(bi*75+j)*6+ch]
__device__ float g_h2[BI*NQ*MID];
__device__ float g_bnscale[2*MID];
__device__ float g_bnshift[2*MID];
__device__ float g_att2[BJ*WAY*HW];    // [(bj*5+i)*36+y]

// ---------------- K1: prototypes ----------------
__global__ void k1_protos(const float* __restrict__ sup, const float* __restrict__ st) {
    int b = blockIdx.y;
    int idx = blockIdx.x * 256 + threadIdx.x;          // < 18432
    __shared__ float st_s[NS*WAY];
    if (threadIdx.x < NS*WAY) st_s[threadIdx.x] = st[b*NS*WAY + threadIdx.x];
    __syncthreads();
    int c = idx / HW, x = idx % HW;
    float acc[WAY]; float cnt[WAY];
#pragma unroll
    for (int i = 0; i < WAY; i++) { acc[i] = 0.f; cnt[i] = 0.f; }
    const float* sb = sup + (size_t)b*NS*C*HW + (size_t)c*HW + x;
    for (int n = 0; n < NS; n++) {
        float v = sb[(size_t)n*C*HW];
#pragma unroll
        for (int i = 0; i < WAY; i++) { float w = st_s[n*WAY+i]; acc[i] += w*v; cnt[i] += w; }
    }
#pragma unroll
    for (int i = 0; i < WAY; i++)
        g_protosT[((size_t)(b*WAY+i)*HW + x)*C + c] = acc[i] / cnt[i];
}

// ---------------- K1b: inv1 + f1nbar + W1p ----------------
__global__ void k1b_norms(const float* __restrict__ w1) {
    int bi = blockIdx.x;                                // 0..39
    __shared__ float inv1_s[HW];
    __shared__ float wi1[MID*HW];
    int t = threadIdx.x;                                // 512
    int w = t >> 5, lane = t & 31;
    const float* p = g_protosT + (size_t)bi*HW*C;
    for (int x = w; x < HW; x += 16) {
        float s0 = 0.f, s1 = 0.f;
        for (int c = lane; c < C; c += 64) {
            float v0 = p[x*C + c];      s0 += v0*v0;
            float v1 = p[x*C + c + 32]; s1 += v1*v1;
        }
        float s = s0 + s1;
#pragma unroll
        for (int o = 16; o; o >>= 1) s += __shfl_down_sync(0xffffffffu, s, o);
        if (lane == 0) {
            float inv = 1.f / fmaxf(sqrtf(s), 1e-12f);
            inv1_s[x] = inv;
            g_inv1[bi*HW + x] = inv;
        }
    }
    __syncthreads();
    if (t < MID*HW) wi1[t] = w1[t] * inv1_s[t % HW];
    __syncthreads();
    int c = t;
    float accb = 0.f, a0=0.f,a1=0.f,a2=0.f,a3=0.f,a4=0.f,a5=0.f;
#pragma unroll 4
    for (int x = 0; x < HW; x++) {
        float pv = p[x*C + c];
        accb += pv * inv1_s[x];
        a0 += pv*wi1[0*HW+x]; a1 += pv*wi1[1*HW+x]; a2 += pv*wi1[2*HW+x];
        a3 += pv*wi1[3*HW+x]; a4 += pv*wi1[4*HW+x]; a5 += pv*wi1[5*HW+x];
    }
    g_f1nbar[bi*C + c] = accb * (1.f/HW);
    float* wp = g_w1p + (size_t)bi*MID*C;
    wp[0*C+c]=a0; wp[1*C+c]=a1; wp[2*C+c]=a2; wp[3*C+c]=a3; wp[4*C+c]=a4; wp[5*C+c]=a5;
}

// ---------------- K2: inv2 + f2nbar + W1q ----------------
__global__ void k2_qnorms(const float* __restrict__ query, const float* __restrict__ w1) {
    extern __shared__ float qs[];                       // [512][37]
    __shared__ float red[8*HW];
    __shared__ float inv2_s[HW];
    __shared__ float wi[MID*HW];
    int bj = blockIdx.x;
    const float* q = query + (size_t)bj*C*HW;
    int t = threadIdx.x;                                // 512
    for (int k = t; k < C*HW; k += 512) qs[(k/HW)*QPAD + k%HW] = q[k];
    __syncthreads();
    if (t < 8*HW) {
        int y = t % HW, g = t / HW;
        float ss = 0.f;
        for (int c = g; c < C; c += 8) { float v = qs[c*QPAD + y]; ss += v*v; }
        red[g*HW + y] = ss;
    }
    __syncthreads();
    if (t < HW) {
        float s = 0.f;
#pragma unroll
        for (int gg = 0; gg < 8; gg++) s += red[gg*HW + t];
        float inv = 1.f / fmaxf(sqrtf(s), 1e-12f);
        inv2_s[t] = inv;
        g_inv2[bj*HW + t] = inv;
    }
    __syncthreads();
    if (t < MID*HW) wi[t] = w1[t] * inv2_s[t % HW];
    __syncthreads();
    float* wq = g_w1q + (size_t)bj*MID*C;
    int c = t;
    float accb=0.f, a0=0.f,a1=0.f,a2=0.f,a3=0.f,a4=0.f,a5=0.f;
#pragma unroll 4
    for (int yy = 0; yy < HW; yy++) {
        float qv = qs[c*QPAD + yy];
        accb += qv * inv2_s[yy];
        a0 += qv*wi[0*HW+yy]; a1 += qv*wi[1*HW+yy]; a2 += qv*wi[2*HW+yy];
        a3 += qv*wi[3*HW+yy]; a4 += qv*wi[4*HW+yy]; a5 += qv*wi[5*HW+yy];
    }
    g_f2nbar[bj*C + c] = accb * (1.f/HW);
    wq[0*C+c]=a0; wq[1*C+c]=a1; wq[2*C+c]=a2; wq[3*C+c]=a3; wq[4*C+c]=a4; wq[5*C+c]=a5;
}

// ---------------- KC: h1/h2 (60 dot-512 per bj; L2-served, no smem) ----------------
__global__ void kc_h(const float* __restrict__ b1) {
    int bj = blockIdx.x; int b = bj / NQ, j = bj % NQ;
    int t = threadIdx.x;                                // 256
    int w = t >> 5, lane = t & 31;
    for (int r = w; r < 2*WAY*MID; r += 8) {
        int path = r / (WAY*MID);
        int i = (r % (WAY*MID)) / MID, ch = r % MID;
        int bi = b*WAY + i;
        const float* va; const float* vb;
        if (path == 0) { va = g_f1nbar + (size_t)bi*C;           vb = g_w1q + ((size_t)bj*MID + ch)*C; }
        else           { va = g_w1p   + ((size_t)bi*MID + ch)*C; vb = g_f2nbar + (size_t)bj*C; }
        float s = 0.f;
        for (int c = lane; c < C; c += 32) s += va[c] * vb[c];
#pragma unroll
        for (int o = 16; o; o >>= 1) s += __shfl_down_sync(0xffffffffu, s, o);
        if (lane == 0) {
            float h = s + b1[ch];
            if (path == 0) g_h1[((size_t)bi*NQ + j)*MID + ch] = h;
            else           g_h2[((size_t)bi*NQ + j)*MID + ch] = h;
        }
    }
}

// ---------------- K4: deterministic BN stats ----------------
__global__ void k4_bn(const float* __restrict__ gamma, const float* __restrict__ beta) {
    int p = blockIdx.x / MID, ch = blockIdx.x % MID;
    const float* h = p ? g_h2 : g_h1;
    int t = threadIdx.x;                                // 256
    double s = 0.0, sq = 0.0;
    for (int n = t; n < BI*NQ; n += 256) {
        double v = (double)h[n*MID + ch];
        s += v; sq += v*v;
    }
    __shared__ double rs[256], rq[256];
    rs[t] = s; rq[t] = sq;
    __syncthreads();
    for (int o = 128; o; o >>= 1) {
        if (t < o) { rs[t] += rs[t+o]; rq[t] += rq[t+o]; }
        __syncthreads();
    }
    if (t == 0) {
        double mu  = rs[0] / 3000.0;
        double var = rq[0] / 3000.0 - mu*mu;
        float sd = sqrtf((float)var + 1e-5f);
        float sc = gamma[ch] / sd;
        g_bnscale[p*MID + ch] = sc;
        g_bnshift[p*MID + ch] = beta[ch] - (float)mu * sc;
    }
}

// ---------------- K5: per-(b,j), all i batched, 512 threads ----------------
__global__ void k5_attn(const float* __restrict__ query,
                        const float* __restrict__ w2, const float* __restrict__ b2,
                        float* __restrict__ out_cls) {
    extern __shared__ __align__(16) float sm[];
    float* qs     = sm;                  // [512][37]
    float* vu     = qs + C*QPAD;         // [5][512]: v1, later u
    float* pp     = vu + WAY*C;          // [5][512]
    float* inv1_s = pp + WAY*C;          // 180
    float* inv2_s = inv1_s + WAY*HW;     // 36
    float* w2_s   = inv2_s + HW;         // 216
    float* b2_s   = w2_s + MID*HW;       // 36
    float* scl    = b2_s + HW;           // 12
    float* shf    = scl + 2*MID;         // 12
    float* wv     = shf + 2*MID;         // 180
    float* coef2  = wv + WAY*HW;         // 180
    float* s_s    = coef2 + WAY*HW;      // 180
    float* att_s  = s_s + WAY*HW;        // 180
    float* red    = att_s + WAY*HW;      // 80
    float* pninv  = red + 80;            // 8

    int bj = blockIdx.x; int b = bj / NQ, j = bj % NQ;
    int t = threadIdx.x;                                // 512
    int w = t >> 5, lane = t & 31;
    const float* q = query + (size_t)bj*C*HW;
    const float* pbase = g_protosT + (size_t)b*WAY*HW*C;

    for (int k = t; k < C*HW; k += 512) qs[(k/HW)*QPAD + k%HW] = q[k];
    if (t < WAY*HW) inv1_s[t] = g_inv1[b*WAY*HW + t];
    if (t < HW) inv2_s[t] = g_inv2[bj*HW + t];
    if (t < MID*HW) w2_s[t] = w2[t];
    if (t < HW) b2_s[t] = b2[t];
    if (t < 2*MID) { scl[t] = g_bnscale[t]; shf[t] = g_bnshift[t]; }
    __syncthreads();

    // prologue: attention pre-activations -> wv (path1 weights), coef2 (path2)
    if (t < WAY*HW) {
        int i = t / HW, y = t % HW;
        const float* h1p = g_h1 + ((size_t)(b*WAY+i)*NQ + j)*MID;
        const float* h2p = g_h2 + ((size_t)(b*WAY+i)*NQ + j)*MID;
        float a1 = b2_s[y], a2 = b2_s[y];
#pragma unroll
        for (int ch = 0; ch < MID; ch++) {
            float r1 = fmaxf(h1p[ch]*scl[ch]     + shf[ch],     0.f);
            float r2 = fmaxf(h2p[ch]*scl[MID+ch] + shf[MID+ch], 0.f);
            a1 += w2_s[y*MID + ch] * r1;
            a2 += w2_s[y*MID + ch] * r2;
        }
        wv[t]    = inv2_s[y] * a1 * (1.f/HW);
        coef2[t] = inv1_s[t] * a2 * (1.f/HW);
    }
    __syncthreads();

    // pass1: v1[i][c] from query (one c per thread)
    {
        int c = t;
        float a0=0.f,a1=0.f,a2=0.f,a3=0.f,a4=0.f;
#pragma unroll 4
        for (int y = 0; y < HW; y++) {
            float qv = qs[c*QPAD + y];
            a0 += qv*wv[0*HW+y]; a1 += qv*wv[1*HW+y]; a2 += qv*wv[2*HW+y];
            a3 += qv*wv[3*HW+y]; a4 += qv*wv[4*HW+y];
        }
        vu[0*C+c]=a0; vu[1*C+c]=a1; vu[2*C+c]=a2; vu[3*C+c]=a3; vu[4*C+c]=a4;
    }
    __syncthreads();

    // pass2: s1[i][x] = inv1 * p[i,x,:].v1  (warp per row, 16 warps)
    for (int r = w; r < WAY*HW; r += 16) {
        int i = r / HW, x = r % HW;
        const float* p = pbase + (size_t)(i*HW + x)*C;
        const float* v = vu + i*C;
        float s = 0.f;
        for (int c = lane; c < C; c += 32) s += p[c]*v[c];
#pragma unroll
        for (int o = 16; o; o >>= 1) s += __shfl_down_sync(0xffffffffu, s, o);
        if (lane == 0) s_s[r] = s * inv1_s[r];
    }
    __syncthreads();

    // softmax1 over x (+1): warp i handles row i
    if (w < WAY) {
        int i = w;
        float v0 = s_s[i*HW + lane];
        float v1v = (lane < HW-32) ? s_s[i*HW + 32 + lane] : -1e30f;
        float mx = fmaxf(v0, v1v);
#pragma unroll
        for (int o = 16; o; o >>= 1) mx = fmaxf(mx, __shfl_xor_sync(0xffffffffu, mx, o));
        float e0 = expf((v0 - mx) * 40.f);
        float e1 = (lane < HW-32) ? expf((v1v - mx) * 40.f) : 0.f;
        float sum = e0 + e1;
#pragma unroll
        for (int o = 16; o; o >>= 1) sum += __shfl_xor_sync(0xffffffffu, sum, o);
        float inv = 1.f / sum;
        att_s[i*HW + lane] = e0*inv + 1.f;
        if (lane < HW-32) att_s[i*HW + 32 + lane] = e1*inv + 1.f;
    }
    __syncthreads();

    // pass3: pp[i][c] (att1-pooled protos) and u[i][c] (coef2-pooled), + ||pp|| partials
    {
        int c = t;
        float sq[WAY];
#pragma unroll
        for (int i = 0; i < WAY; i++) {
            const float* p = pbase + (size_t)i*HW*C + c;
            float ap = 0.f, au = 0.f;
#pragma unroll 4
            for (int x = 0; x < HW; x++) {
                float pv = p[(size_t)x*C];
                ap += pv * att_s[i*HW + x];
                au += pv * coef2[i*HW + x];
            }
            ap *= (1.f/HW);
            pp[i*C + c] = ap;
            vu[i*C + c] = au;          // overwrite dead v1
            sq[i] = ap*ap;
        }
#pragma unroll
        for (int i = 0; i < WAY; i++) {
            float s = sq[i];
#pragma unroll
            for (int o = 16; o; o >>= 1) s += __shfl_down_sync(0xffffffffu, s, o);
            if (lane == 0) red[i*16 + w] = s;
        }
    }
    __syncthreads();
    if (t < WAY) {
        float s = 0.f;
#pragma unroll
        for (int g = 0; g < 16; g++) s += red[t*16 + g];
        pninv[t] = 1.f / fmaxf(sqrtf(s), 1e-12f);
    }
    __syncthreads();

    // pass4: cls_scores[i][y] and s2[i][y]  (warp per row)
    for (int r = w; r < WAY*HW; r += 16) {
        int i = r / HW, y = r % HW;
        float d1 = 0.f, d2 = 0.f;
        for (int c = lane; c < C; c += 32) {
            float qv = qs[c*QPAD + y];
            d1 += qv * pp[i*C + c];
            d2 += qv * vu[i*C + c];
        }
#pragma unroll
        for (int o = 16; o; o >>= 1) {
            d1 += __shfl_down_sync(0xffffffffu, d1, o);
            d2 += __shfl_down_sync(0xffffffffu, d2, o);
        }
        if (lane == 0) {
            out_cls[((size_t)bj*WAY + i)*HW + y] = 7.f * pninv[i] * inv2_s[y] * d1;
            s_s[r] = inv2_s[y] * d2;
        }
    }
    __syncthreads();

    // softmax2 over y (+1) -> g_att2
    if (w < WAY) {
        int i = w;
        float v0 = s_s[i*HW + lane];
        float v1v = (lane < HW-32) ? s_s[i*HW + 32 + lane] : -1e30f;
        float mx = fmaxf(v0, v1v);
#pragma unroll
        for (int o = 16; o; o >>= 1) mx = fmaxf(mx, __shfl_xor_sync(0xffffffffu, mx, o));
        float e0 = expf((v0 - mx) * 40.f);
        float e1 = (lane < HW-32) ? expf((v1v - mx) * 40.f) : 0.f;
        float sum = e0 + e1;
#pragma unroll
        for (int o = 16; o; o >>= 1) sum += __shfl_xor_sync(0xffffffffu, sum, o);
        float inv = 1.f / sum;
        float* a2p = g_att2 + ((size_t)bj*WAY + i)*HW;
        a2p[lane] = e0*inv + 1.f;
        if (lane < HW-32) a2p[32 + lane] = e1*inv + 1.f;
    }
}
#define K5_SMEM ((C*QPAD + 2*WAY*C + 6*WAY*HW + 2*HW + MID*HW + 4*MID + 88)*4 + 64)

// ---------------- K6: logits ----------------
__global__ void k6_logits(const float* __restrict__ query, const float* __restrict__ qt,
                          const float* __restrict__ clsw, const float* __restrict__ clsb,
                          float* __restrict__ out_logits) {
    __shared__ __align__(16) float qs[64*40];
    __shared__ __align__(16) float ws[64*68];
    __shared__ float asel[HW];
    __shared__ float cb[NCLS];
    __shared__ float qt_s[WAY];
    int bj = blockIdx.x;
    int t = threadIdx.x;                                // 144
    if (t < WAY) qt_s[t] = qt[bj*WAY + t];
    if (t < NCLS) cb[t] = clsb[t];
    __syncthreads();
    if (t < HW) {
        float a = 0.f;
#pragma unroll
        for (int i = 0; i < WAY; i++)
            a += qt_s[i] * g_att2[((size_t)bj*WAY + i)*HW + t];
        asel[t] = a;
    }
    int og = t & 15, yg = t >> 4;                       // 16 x 9
    int o0 = og*4, y0 = yg*4;
    float acc[16];
#pragma unroll
    for (int k = 0; k < 16; k++) acc[k] = 0.f;
    const float* q = query + (size_t)bj*C*HW;
    for (int c0 = 0; c0 < C; c0 += 64) {
        __syncthreads();
        for (int k = t; k < 64*HW; k += 144) {
            int c = k / HW, y = k % HW;
            qs[c*40 + y] = q[(c0 + c)*HW + y];
        }
        for (int k = t; k < 64*64; k += 144) {
            int c = k & 63, o = k >> 6;
            ws[c*68 + o] = clsw[o*C + c0 + c];
        }
        __syncthreads();
#pragma unroll 4
        for (int cc = 0; cc < 64; cc++) {
            float4 wvv = *(const float4*)&ws[cc*68 + o0];
            float4 qv = *(const float4*)&qs[cc*40 + y0];
            acc[0]  += wvv.x*qv.x; acc[1]  += wvv.x*qv.y; acc[2]  += wvv.x*qv.z; acc[3]  += wvv.x*qv.w;
            acc[4]  += wvv.y*qv.x; acc[5]  += wvv.y*qv.y; acc[6]  += wvv.y*qv.z; acc[7]  += wvv.y*qv.w;
            acc[8]  += wvv.z*qv.x; acc[9]  += wvv.z*qv.y; acc[10] += wvv.z*qv.z; acc[11] += wvv.z*qv.w;
            acc[12] += wvv.w*qv.x; acc[13] += wvv.w*qv.y; acc[14] += wvv.w*qv.z; acc[15] += wvv.w*qv.w;
        }
    }
    float* op = out_logits + (size_t)bj*NCLS*HW;
#pragma unroll
    for (int oo = 0; oo < 4; oo++)
#pragma unroll
        for (int yy = 0; yy < 4; yy++)
            op[(o0+oo)*HW + y0 + yy] = asel[y0+yy]*acc[oo*4+yy] + cb[o0+oo];
}

// ---------------- launch ----------------
extern "C" void kernel_launch(void* const* d_in, const int* in_sizes, int n_in,
                              void* d_out, int out_size) {
    const float* sup   = (const float*)d_in[0];
    const float* query = (const float*)d_in[1];
    const float* st    = (const float*)d_in[2];
    const float* qt    = (const float*)d_in[3];
    const float* w1    = (const float*)d_in[4];
    const float* b1    = (const float*)d_in[5];
    const float* gamma = (const float*)d_in[6];
    const float* beta  = (const float*)d_in[7];
    const float* w2    = (const float*)d_in[8];
    const float* b2    = (const float*)d_in[9];
    const float* clsw  = (const float*)d_in[10];
    const float* clsb  = (const float*)d_in[11];
    float* out = (float*)d_out;

    cudaFuncSetAttribute(k5_attn, cudaFuncAttributeMaxDynamicSharedMemorySize, K5_SMEM);
    cudaFuncSetAttribute(k2_qnorms, cudaFuncAttributeMaxDynamicSharedMemorySize, C*QPAD*4);

    k1_protos<<<dim3(72, B), 256>>>(sup, st);
    k1b_norms<<<BI, 512>>>(w1);
    k2_qnorms<<<BJ, 512, C*QPAD*4>>>(query, w1);
    kc_h<<<BJ, 256>>>(b1);
    k4_bn<<<2*MID, 256>>>(gamma, beta);
    k5_attn<<<BJ, 512, K5_SMEM>>>(query, w2, b2, out + LOGITS_N);
    k6_logits<<<BJ, 144>>>(query, qt, clsw, clsb, out);
}

// round 10
// speedup vs baseline: 1.8193x; 1.0523x over previous
#include <cuda_runtime.h>
#include <math.h>

#define B 8
#define NS 25
#define NQ 75
#define WAY 5
#define C 512
#define HW 36
#define MID 6
#define NCLS 64
#define BJ (B*NQ)      // 600
#define BI (B*WAY)     // 40
#define LOGITS_N (BJ*NCLS*HW)   // 1382400
#define QPAD 37

// ---------------- f32x2 helpers (sm_103a packed fp32) ----------------
__device__ __forceinline__ unsigned long long pack2(float lo, float hi) {
    unsigned long long r;
    asm("mov.b64 %0, {%1, %2};" : "=l"(r) : "f"(lo), "f"(hi));
    return r;
}
__device__ __forceinline__ void fma2(unsigned long long& d, unsigned long long a, unsigned long long b) {
    asm("fma.rn.f32x2 %0, %1, %2, %3;" : "=l"(d) : "l"(a), "l"(b), "l"(d));
}
__device__ __forceinline__ void unpack2(unsigned long long v, float& lo, float& hi) {
    asm("mov.b64 {%0, %1}, %2;" : "=f"(lo), "=f"(hi) : "l"(v));
}

// ---------------- scratch ----------------
__device__ float g_protosT[BI*HW*C];   // [bi][x][c]
__device__ float g_inv1[BI*HW];
__device__ float g_f1nbar[BI*C];
__device__ float g_inv2[BJ*HW];
__device__ float g_f2nbar[BJ*C];
__device__ float g_w1q[BJ*MID*C];
__device__ float g_w1p[BI*MID*C];
__device__ float g_h1[BI*NQ*MID];
__device__ float g_h2[BI*NQ*MID];
__device__ float g_bnscale[2*MID];
__device__ float g_bnshift[2*MID];

// ---------------- K1: prototypes ----------------
__global__ void k1_protos(const float* __restrict__ sup, const float* __restrict__ st) {
    int b = blockIdx.y;
    int idx = blockIdx.x * 256 + threadIdx.x;          // < 18432
    __shared__ float st_s[NS*WAY];
    if (threadIdx.x < NS*WAY) st_s[threadIdx.x] = st[b*NS*WAY + threadIdx.x];
    __syncthreads();
    int c = idx / HW, x = idx % HW;
    float acc[WAY]; float cnt[WAY];
#pragma unroll
    for (int i = 0; i < WAY; i++) { acc[i] = 0.f; cnt[i] = 0.f; }
    const float* sb = sup + (size_t)b*NS*C*HW + (size_t)c*HW + x;
    for (int n = 0; n < NS; n++) {
        float v = sb[(size_t)n*C*HW];
#pragma unroll
        for (int i = 0; i < WAY; i++) { float w = st_s[n*WAY+i]; acc[i] += w*v; cnt[i] += w; }
    }
#pragma unroll
    for (int i = 0; i < WAY; i++)
        g_protosT[((size_t)(b*WAY+i)*HW + x)*C + c] = acc[i] / cnt[i];
}

// ---------------- K1b: inv1 + f1nbar + W1p ----------------
__global__ void k1b_norms(const float* __restrict__ w1) {
    int bi = blockIdx.x;                                // 0..39
    __shared__ float inv1_s[HW];
    __shared__ float wi1[MID*HW];
    int t = threadIdx.x;                                // 512
    int w = t >> 5, lane = t & 31;
    const float* p = g_protosT + (size_t)bi*HW*C;
    for (int x = w; x < HW; x += 16) {
        float s0 = 0.f, s1 = 0.f;
        for (int c = lane; c < C; c += 64) {
            float v0 = p[x*C + c];      s0 += v0*v0;
            float v1 = p[x*C + c + 32]; s1 += v1*v1;
        }
        float s = s0 + s1;
#pragma unroll
        for (int o = 16; o; o >>= 1) s += __shfl_down_sync(0xffffffffu, s, o);
        if (lane == 0) {
            float inv = 1.f / fmaxf(sqrtf(s), 1e-12f);
            inv1_s[x] = inv;
            g_inv1[bi*HW + x] = inv;
        }
    }
    __syncthreads();
    if (t < MID*HW) wi1[t] = w1[t] * inv1_s[t % HW];
    __syncthreads();
    int c = t;
    float accb = 0.f, a0=0.f,a1=0.f,a2=0.f,a3=0.f,a4=0.f,a5=0.f;
#pragma unroll 4
    for (int x = 0; x < HW; x++) {
        float pv = p[x*C + c];
        accb += pv * inv1_s[x];
        a0 += pv*wi1[0*HW+x]; a1 += pv*wi1[1*HW+x]; a2 += pv*wi1[2*HW+x];
        a3 += pv*wi1[3*HW+x]; a4 += pv*wi1[4*HW+x]; a5 += pv*wi1[5*HW+x];
    }
    g_f1nbar[bi*C + c] = accb * (1.f/HW);
    float* wp = g_w1p + (size_t)bi*MID*C;
    wp[0*C+c]=a0; wp[1*C+c]=a1; wp[2*C+c]=a2; wp[3*C+c]=a3; wp[4*C+c]=a4; wp[5*C+c]=a5;
}

// ---------------- K2: inv2 + f2nbar + W1q ----------------
__global__ void k2_qnorms(const float* __restrict__ query, const float* __restrict__ w1) {
    extern __shared__ float qs[];                       // [512][37]
    __shared__ float red[8*HW];
    __shared__ float inv2_s[HW];
    __shared__ float wi[MID*HW];
    int bj = blockIdx.x;
    const float* q = query + (size_t)bj*C*HW;
    int t = threadIdx.x;                                // 512
    for (int k = t; k < C*HW; k += 512) qs[(k/HW)*QPAD + k%HW] = q[k];
    __syncthreads();
    if (t < 8*HW) {
        int y = t % HW, g = t / HW;
        float ss = 0.f;
        for (int c = g; c < C; c += 8) { float v = qs[c*QPAD + y]; ss += v*v; }
        red[g*HW + y] = ss;
    }
    __syncthreads();
    if (t < HW) {
        float s = 0.f;
#pragma unroll
        for (int gg = 0; gg < 8; gg++) s += red[gg*HW + t];
        float inv = 1.f / fmaxf(sqrtf(s), 1e-12f);
        inv2_s[t] = inv;
        g_inv2[bj*HW + t] = inv;
    }
    __syncthreads();
    if (t < MID*HW) wi[t] = w1[t] * inv2_s[t % HW];
    __syncthreads();
    float* wq = g_w1q + (size_t)bj*MID*C;
    int c = t;
    float accb=0.f, a0=0.f,a1=0.f,a2=0.f,a3=0.f,a4=0.f,a5=0.f;
#pragma unroll 4
    for (int yy = 0; yy < HW; yy++) {
        float qv = qs[c*QPAD + yy];
        accb += qv * inv2_s[yy];
        a0 += qv*wi[0*HW+yy]; a1 += qv*wi[1*HW+yy]; a2 += qv*wi[2*HW+yy];
        a3 += qv*wi[3*HW+yy]; a4 += qv*wi[4*HW+yy]; a5 += qv*wi[5*HW+yy];
    }
    g_f2nbar[bj*C + c] = accb * (1.f/HW);
    wq[0*C+c]=a0; wq[1*C+c]=a1; wq[2*C+c]=a2; wq[3*C+c]=a3; wq[4*C+c]=a4; wq[5*C+c]=a5;
}

// ---------------- KC: h1/h2 (L2-served, no smem; measured 17-18us) ----------------
__global__ void kc_h(const float* __restrict__ b1) {
    int bj = blockIdx.x; int b = bj / NQ, j = bj % NQ;
    int t = threadIdx.x;                                // 256
    int w = t >> 5, lane = t & 31;
    for (int r = w; r < 2*WAY*MID; r += 8) {
        int path = r / (WAY*MID);
        int i = (r % (WAY*MID)) / MID, ch = r % MID;
        int bi = b*WAY + i;
        const float* va; const float* vb;
        if (path == 0) { va = g_f1nbar + (size_t)bi*C;           vb = g_w1q + ((size_t)bj*MID + ch)*C; }
        else           { va = g_w1p   + ((size_t)bi*MID + ch)*C; vb = g_f2nbar + (size_t)bj*C; }
        float s = 0.f;
        for (int c = lane; c < C; c += 32) s += va[c] * vb[c];
#pragma unroll
        for (int o = 16; o; o >>= 1) s += __shfl_down_sync(0xffffffffu, s, o);
        if (lane == 0) {
            float h = s + b1[ch];
            if (path == 0) g_h1[((size_t)bi*NQ + j)*MID + ch] = h;
            else           g_h2[((size_t)bi*NQ + j)*MID + ch] = h;
        }
    }
}

// ---------------- K4: deterministic BN stats ----------------
__global__ void k4_bn(const float* __restrict__ gamma, const float* __restrict__ beta) {
    int p = blockIdx.x / MID, ch = blockIdx.x % MID;
    const float* h = p ? g_h2 : g_h1;
    int t = threadIdx.x;                                // 256
    double s = 0.0, sq = 0.0;
    for (int n = t; n < BI*NQ; n += 256) {
        double v = (double)h[n*MID + ch];
        s += v; sq += v*v;
    }
    __shared__ double rs[256], rq[256];
    rs[t] = s; rq[t] = sq;
    __syncthreads();
    for (int o = 128; o; o >>= 1) {
        if (t < o) { rs[t] += rs[t+o]; rq[t] += rq[t+o]; }
        __syncthreads();
    }
    if (t == 0) {
        double mu  = rs[0] / 3000.0;
        double var = rq[0] / 3000.0 - mu*mu;
        float sd = sqrtf((float)var + 1e-5f);
        float sc = gamma[ch] / sd;
        g_bnscale[p*MID + ch] = sc;
        g_bnshift[p*MID + ch] = beta[ch] - (float)mu * sc;
    }
}

// ---------------- K5: fused attention + cls_scores + logits GEMM ----------------
__global__ __launch_bounds__(512, 2)
void k5_fused(const float* __restrict__ query, const float* __restrict__ qt,
              const float* __restrict__ w2, const float* __restrict__ b2,
              const float* __restrict__ clsw, const float* __restrict__ clsb,
              float* __restrict__ out_logits, float* __restrict__ out_cls) {
    extern __shared__ __align__(16) float sm[];
    float* qs     = sm;                  // [512][37]
    float* vu     = qs + C*QPAD;         // [5][512]: v1, later u; later ws alias
    float* pp     = vu + WAY*C;          // [5][512]
    float* inv1_s = pp + WAY*C;          // 180
    float* inv2_s = inv1_s + WAY*HW;     // 36
    float* w2_s   = inv2_s + HW;         // 216
    float* b2_s   = w2_s + MID*HW;       // 36
    float* scl    = b2_s + HW;           // 12
    float* shf    = scl + 2*MID;         // 12
    float* wv     = shf + 2*MID;         // 180
    float* coef2  = wv + WAY*HW;         // 180
    float* s_s    = coef2 + WAY*HW;      // 180
    float* att_s  = s_s + WAY*HW;        // 180
    float* red    = att_s + WAY*HW;      // 80
    float* pninv  = red + 80;            // 8
    float* asel   = pninv + 8;           // 36
    float* cb     = asel + HW;           // 64
    float* qt_s   = cb + NCLS;           // 8
    float* ws     = vu;                  // [64][68] alias (4352 <= 5120), used after pass4

    int bj = blockIdx.x; int b = bj / NQ, j = bj % NQ;
    int t = threadIdx.x;                                // 512
    int w = t >> 5, lane = t & 31;
    const float* q = query + (size_t)bj*C*HW;
    const float* pbase = g_protosT + (size_t)b*WAY*HW*C;

    for (int k = t; k < C*HW; k += 512) qs[(k/HW)*QPAD + k%HW] = q[k];
    if (t < WAY*HW) inv1_s[t] = g_inv1[b*WAY*HW + t];
    if (t < HW) inv2_s[t] = g_inv2[bj*HW + t];
    if (t < MID*HW) w2_s[t] = w2[t];
    if (t < HW) b2_s[t] = b2[t];
    if (t < 2*MID) { scl[t] = g_bnscale[t]; shf[t] = g_bnshift[t]; }
    if (t < NCLS) cb[t] = clsb[t];
    if (t < WAY) qt_s[t] = qt[bj*WAY + t];
    __syncthreads();

    // prologue: BN+relu+conv2 pre-activations -> wv (path1), coef2 (path2)
    if (t < WAY*HW) {
        int i = t / HW, y = t % HW;
        const float* h1p = g_h1 + ((size_t)(b*WAY+i)*NQ + j)*MID;
        const float* h2p = g_h2 + ((size_t)(b*WAY+i)*NQ + j)*MID;
        float a1 = b2_s[y], a2 = b2_s[y];
#pragma unroll
        for (int ch = 0; ch < MID; ch++) {
            float r1 = fmaxf(h1p[ch]*scl[ch]     + shf[ch],     0.f);
            float r2 = fmaxf(h2p[ch]*scl[MID+ch] + shf[MID+ch], 0.f);
            a1 += w2_s[y*MID + ch] * r1;
            a2 += w2_s[y*MID + ch] * r2;
        }
        wv[t]    = inv2_s[y] * a1 * (1.f/HW);
        coef2[t] = inv1_s[t] * a2 * (1.f/HW);
    }
    __syncthreads();

    // pass1: v1[i][c] from query (one c per thread)
    {
        int c = t;
        float a0=0.f,a1=0.f,a2=0.f,a3=0.f,a4=0.f;
#pragma unroll 4
        for (int y = 0; y < HW; y++) {
            float qv = qs[c*QPAD + y];
            a0 += qv*wv[0*HW+y]; a1 += qv*wv[1*HW+y]; a2 += qv*wv[2*HW+y];
            a3 += qv*wv[3*HW+y]; a4 += qv*wv[4*HW+y];
        }
        vu[0*C+c]=a0; vu[1*C+c]=a1; vu[2*C+c]=a2; vu[3*C+c]=a3; vu[4*C+c]=a4;
    }
    __syncthreads();

    // pass2: s1[i][x] = inv1 * p[i,x,:].v1 (warp per row)
    for (int r = w; r < WAY*HW; r += 16) {
        int i = r / HW, x = r % HW;
        const float* p = pbase + (size_t)(i*HW + x)*C;
        const float* v = vu + i*C;
        float s = 0.f;
        for (int c = lane; c < C; c += 32) s += p[c]*v[c];
#pragma unroll
        for (int o = 16; o; o >>= 1) s += __shfl_down_sync(0xffffffffu, s, o);
        if (lane == 0) s_s[r] = s * inv1_s[r];
    }
    __syncthreads();

    // softmax1 over x (+1): warp i -> row i
    if (w < WAY) {
        int i = w;
        float v0 = s_s[i*HW + lane];
        float v1v = (lane < HW-32) ? s_s[i*HW + 32 + lane] : -1e30f;
        float mx = fmaxf(v0, v1v);
#pragma unroll
        for (int o = 16; o; o >>= 1) mx = fmaxf(mx, __shfl_xor_sync(0xffffffffu, mx, o));
        float e0 = expf((v0 - mx) * 40.f);
        float e1 = (lane < HW-32) ? expf((v1v - mx) * 40.f) : 0.f;
        float sum = e0 + e1;
#pragma unroll
        for (int o = 16; o; o >>= 1) sum += __shfl_xor_sync(0xffffffffu, sum, o);
        float inv = 1.f / sum;
        att_s[i*HW + lane] = e0*inv + 1.f;
        if (lane < HW-32) att_s[i*HW + 32 + lane] = e1*inv + 1.f;
    }
    __syncthreads();

    // pass3: pp[i][c] (att1-pooled) and u[i][c] (coef2-pooled) in one protos read
    {
        int c = t;
        float sq[WAY];
#pragma unroll
        for (int i = 0; i < WAY; i++) {
            const float* p = pbase + (size_t)i*HW*C + c;
            float ap = 0.f, au = 0.f;
#pragma unroll 4
            for (int x = 0; x < HW; x++) {
                float pv = p[(size_t)x*C];
                ap += pv * att_s[i*HW + x];
                au += pv * coef2[i*HW + x];
            }
            ap *= (1.f/HW);
            pp[i*C + c] = ap;
            vu[i*C + c] = au;
            sq[i] = ap*ap;
        }
#pragma unroll
        for (int i = 0; i < WAY; i++) {
            float s = sq[i];
#pragma unroll
            for (int o = 16; o; o >>= 1) s += __shfl_down_sync(0xffffffffu, s, o);
            if (lane == 0) red[i*16 + w] = s;
        }
    }
    __syncthreads();
    if (t < WAY) {
        float s = 0.f;
#pragma unroll
        for (int g = 0; g < 16; g++) s += red[t*16 + g];
        pninv[t] = 1.f / fmaxf(sqrtf(s), 1e-12f);
    }
    __syncthreads();

    // pass4: cls_scores[i][y] and s2[i][y]
    for (int r = w; r < WAY*HW; r += 16) {
        int i = r / HW, y = r % HW;
        float d1 = 0.f, d2 = 0.f;
        for (int c = lane; c < C; c += 32) {
            float qv = qs[c*QPAD + y];
            d1 += qv * pp[i*C + c];
            d2 += qv * vu[i*C + c];
        }
#pragma unroll
        for (int o = 16; o; o >>= 1) {
            d1 += __shfl_down_sync(0xffffffffu, d1, o);
            d2 += __shfl_down_sync(0xffffffffu, d2, o);
        }
        if (lane == 0) {
            out_cls[((size_t)bj*WAY + i)*HW + y] = 7.f * pninv[i] * inv2_s[y] * d1;
            s_s[r] = inv2_s[y] * d2;
        }
    }
    __syncthreads();

    // softmax2 over y (+1) -> att_s (att2)
    if (w < WAY) {
        int i = w;
        float v0 = s_s[i*HW + lane];
        float v1v = (lane < HW-32) ? s_s[i*HW + 32 + lane] : -1e30f;
        float mx = fmaxf(v0, v1v);
#pragma unroll
        for (int o = 16; o; o >>= 1) mx = fmaxf(mx, __shfl_xor_sync(0xffffffffu, mx, o));
        float e0 = expf((v0 - mx) * 40.f);
        float e1 = (lane < HW-32) ? expf((v1v - mx) * 40.f) : 0.f;
        float sum = e0 + e1;
#pragma unroll
        for (int o = 16; o; o >>= 1) sum += __shfl_xor_sync(0xffffffffu, sum, o);
        float inv = 1.f / sum;
        att_s[i*HW + lane] = e0*inv + 1.f;
        if (lane < HW-32) att_s[i*HW + 32 + lane] = e1*inv + 1.f;
    }
    __syncthreads();

    // asel[y] = sum_i qt[i] * att2[i][y]
    if (t < HW) {
        float a = 0.f;
#pragma unroll
        for (int i = 0; i < WAY; i++) a += qt_s[i] * att_s[i*HW + t];
        asel[t] = a;
    }

    // logits GEMM: out[o][y] = asel[y] * sum_c clsw[o][c]*q[c][y] + cb[o]
    // threads t<144: 4o x 4y register tile; FFMA2 packed over o-pairs.
    int og = t & 15, yg = t >> 4;                       // valid for t < 144
    int o0 = og*4, y0 = yg*4;
    unsigned long long acc2[8];
#pragma unroll
    for (int k = 0; k < 8; k++) acc2[k] = 0ull;

    for (int c0 = 0; c0 < C; c0 += 64) {
        __syncthreads();                                // protect ws (aliases vu/pp)
        for (int k = t; k < 64*64; k += 512) {
            int c = k & 63, o = k >> 6;
            ws[c*68 + o] = clsw[o*C + c0 + c];
        }
        __syncthreads();
        if (t < 144) {
#pragma unroll 4
            for (int cc = 0; cc < 64; cc++) {
                const float* qrow = qs + (c0 + cc)*QPAD + y0;
                unsigned long long qb0 = pack2(qrow[0], qrow[0]);
                unsigned long long qb1 = pack2(qrow[1], qrow[1]);
                unsigned long long qb2 = pack2(qrow[2], qrow[2]);
                unsigned long long qb3 = pack2(qrow[3], qrow[3]);
                unsigned long long w01 = *(const unsigned long long*)&ws[cc*68 + o0];
                unsigned long long w23 = *(const unsigned long long*)&ws[cc*68 + o0 + 2];
                fma2(acc2[0], w01, qb0); fma2(acc2[1], w01, qb1);
                fma2(acc2[2], w01, qb2); fma2(acc2[3], w01, qb3);
                fma2(acc2[4], w23, qb0); fma2(acc2[5], w23, qb1);
                fma2(acc2[6], w23, qb2); fma2(acc2[7], w23, qb3);
            }
        }
    }
    if (t < 144) {
        float* op = out_logits + (size_t)bj*NCLS*HW;
#pragma unroll
        for (int p = 0; p < 2; p++) {
#pragma unroll
            for (int y = 0; y < 4; y++) {
                float lo, hi;
                unpack2(acc2[p*4 + y], lo, hi);
                float a = asel[y0 + y];
                op[(o0 + 2*p    )*HW + y0 + y] = a*lo + cb[o0 + 2*p];
                op[(o0 + 2*p + 1)*HW + y0 + y] = a*hi + cb[o0 + 2*p + 1];
            }
        }
    }
}
#define K5F_SMEM ((C*QPAD + 2*WAY*C + 6*WAY*HW + 2*HW + MID*HW + 4*MID + 88 + HW + NCLS + 8)*4 + 64)

// ---------------- launch ----------------
extern "C" void kernel_launch(void* const* d_in, const int* in_sizes, int n_in,
                              void* d_out, int out_size) {
    const float* sup   = (const float*)d_in[0];
    const float* query = (const float*)d_in[1];
    const float* st    = (const float*)d_in[2];
    const float* qt    = (const float*)d_in[3];
    const float* w1    = (const float*)d_in[4];
    const float* b1    = (const float*)d_in[5];
    const float* gamma = (const float*)d_in[6];
    const float* beta  = (const float*)d_in[7];
    const float* w2    = (const float*)d_in[8];
    const float* b2    = (const float*)d_in[9];
    const float* clsw  = (const float*)d_in[10];
    const float* clsb  = (const float*)d_in[11];
    float* out = (float*)d_out;

    cudaFuncSetAttribute(k5_fused, cudaFuncAttributeMaxDynamicSharedMemorySize, K5F_SMEM);
    cudaFuncSetAttribute(k2_qnorms, cudaFuncAttributeMaxDynamicSharedMemorySize, C*QPAD*4);

    k1_protos<<<dim3(72, B), 256>>>(sup, st);
    k1b_norms<<<BI, 512>>>(w1);
    k2_qnorms<<<BJ, 512, C*QPAD*4>>>(query, w1);
    kc_h<<<BJ, 256>>>(b1);
    k4_bn<<<2*MID, 256>>>(gamma, beta);
    k5_fused<<<BJ, 512, K5F_SMEM>>>(query, qt, w2, b2, clsw, clsb,
                                    out, out + LOGITS_N);
}

// round 14
// speedup vs baseline: 1.8430x; 1.0130x over previous
#include <cuda_runtime.h>
#include <math.h>

#define B 8
#define NS 25
#define NQ 75
#define WAY 5
#define C 512
#define HW 36
#define MID 6
#define NCLS 64
#define BJ (B*NQ)      // 600
#define BI (B*WAY)     // 40
#define LOGITS_N (BJ*NCLS*HW)   // 1382400
#define QPAD 37

// ---------------- f32x2 helpers (sm_103a packed fp32) ----------------
__device__ __forceinline__ unsigned long long pack2(float lo, float hi) {
    unsigned long long r;
    asm("mov.b64 %0, {%1, %2};" : "=l"(r) : "f"(lo), "f"(hi));
    return r;
}
__device__ __forceinline__ void fma2(unsigned long long& d, unsigned long long a, unsigned long long b) {
    asm("fma.rn.f32x2 %0, %1, %2, %3;" : "=l"(d) : "l"(a), "l"(b), "l"(d));
}
__device__ __forceinline__ void unpack2(unsigned long long v, float& lo, float& hi) {
    asm("mov.b64 {%0, %1}, %2;" : "=f"(lo), "=f"(hi) : "l"(v));
}

// ---------------- scratch ----------------
__device__ float g_protosT[BI*HW*C];   // [bi][x][c]
__device__ float g_inv1[BI*HW];
__device__ float g_f1nbar[BI*C];
__device__ float g_inv2[BJ*HW];
__device__ float g_w1p[BI*MID*C];      // [(bi*6+ch)*512+c]
__device__ float g_h1[BI*NQ*MID];
__device__ float g_h2[BI*NQ*MID];
__device__ float g_bnscale[2*MID];
__device__ float g_bnshift[2*MID];

// ---------------- K1: prototypes ----------------
__global__ void k1_protos(const float* __restrict__ sup, const float* __restrict__ st) {
    int b = blockIdx.y;
    int idx = blockIdx.x * 256 + threadIdx.x;          // < 18432
    __shared__ float st_s[NS*WAY];
    if (threadIdx.x < NS*WAY) st_s[threadIdx.x] = st[b*NS*WAY + threadIdx.x];
    __syncthreads();
    int c = idx / HW, x = idx % HW;
    float acc[WAY]; float cnt[WAY];
#pragma unroll
    for (int i = 0; i < WAY; i++) { acc[i] = 0.f; cnt[i] = 0.f; }
    const float* sb = sup + (size_t)b*NS*C*HW + (size_t)c*HW + x;
    for (int n = 0; n < NS; n++) {
        float v = sb[(size_t)n*C*HW];
#pragma unroll
        for (int i = 0; i < WAY; i++) { float w = st_s[n*WAY+i]; acc[i] += w*v; cnt[i] += w; }
    }
#pragma unroll
    for (int i = 0; i < WAY; i++)
        g_protosT[((size_t)(b*WAY+i)*HW + x)*C + c] = acc[i] / cnt[i];
}

// ---------------- K1b: inv1 + f1nbar + W1p ----------------
__global__ void k1b_norms(const float* __restrict__ w1) {
    int bi = blockIdx.x;                                // 0..39
    __shared__ float inv1_s[HW];
    __shared__ float wi1[MID*HW];
    int t = threadIdx.x;                                // 512
    int w = t >> 5, lane = t & 31;
    const float* p = g_protosT + (size_t)bi*HW*C;
    for (int x = w; x < HW; x += 16) {
        float s0 = 0.f, s1 = 0.f;
        for (int c = lane; c < C; c += 64) {
            float v0 = p[x*C + c];      s0 += v0*v0;
            float v1 = p[x*C + c + 32]; s1 += v1*v1;
        }
        float s = s0 + s1;
#pragma unroll
        for (int o = 16; o; o >>= 1) s += __shfl_down_sync(0xffffffffu, s, o);
        if (lane == 0) {
            float inv = 1.f / fmaxf(sqrtf(s), 1e-12f);
            inv1_s[x] = inv;
            g_inv1[bi*HW + x] = inv;
        }
    }
    __syncthreads();
    if (t < MID*HW) wi1[t] = w1[t] * inv1_s[t % HW];
    __syncthreads();
    int c = t;
    float accb = 0.f, a0=0.f,a1=0.f,a2=0.f,a3=0.f,a4=0.f,a5=0.f;
#pragma unroll 4
    for (int x = 0; x < HW; x++) {
        float pv = p[x*C + c];
        accb += pv * inv1_s[x];
        a0 += pv*wi1[0*HW+x]; a1 += pv*wi1[1*HW+x]; a2 += pv*wi1[2*HW+x];
        a3 += pv*wi1[3*HW+x]; a4 += pv*wi1[4*HW+x]; a5 += pv*wi1[5*HW+x];
    }
    g_f1nbar[bi*C + c] = accb * (1.f/HW);
    float* wp = g_w1p + (size_t)bi*MID*C;
    wp[0*C+c]=a0; wp[1*C+c]=a1; wp[2*C+c]=a2; wp[3*C+c]=a3; wp[4*C+c]=a4; wp[5*C+c]=a5;
}

// ---------------- K2: inv2 + (w1q, f2nbar in-register) -> h1/h2 directly ----------------
__global__ void k2_qnorms(const float* __restrict__ query, const float* __restrict__ w1,
                          const float* __restrict__ b1) {
    extern __shared__ float qs[];                       // [512][37]
    __shared__ float red[8*HW];
    __shared__ float inv2_s[HW];
    __shared__ float wi[MID*HW];
    __shared__ float hred[16*64];                       // 16 warps x (30 h1 | pad | 30 h2)
    int bj = blockIdx.x; int b = bj / NQ, j = bj % NQ;
    const float* q = query + (size_t)bj*C*HW;
    int t = threadIdx.x;                                // 512
    int w = t >> 5, lane = t & 31;
    for (int k = t; k < C*HW; k += 512) qs[(k/HW)*QPAD + k%HW] = q[k];
    __syncthreads();
    if (t < 8*HW) {
        int y = t % HW, g = t / HW;
        float ss = 0.f;
        for (int c = g; c < C; c += 8) { float v = qs[c*QPAD + y]; ss += v*v; }
        red[g*HW + y] = ss;
    }
    __syncthreads();
    if (t < HW) {
        float s = 0.f;
#pragma unroll
        for (int gg = 0; gg < 8; gg++) s += red[gg*HW + t];
        float inv = 1.f / fmaxf(sqrtf(s), 1e-12f);
        inv2_s[t] = inv;
        g_inv2[bj*HW + t] = inv;
    }
    __syncthreads();
    if (t < MID*HW) wi[t] = w1[t] * inv2_s[t % HW];
    __syncthreads();
    // per-thread c = t: w1q[ch] in a[], f2nbar in f2n
    int c = t;
    float a[MID]; float accb = 0.f;
#pragma unroll
    for (int ch = 0; ch < MID; ch++) a[ch] = 0.f;
#pragma unroll 4
    for (int yy = 0; yy < HW; yy++) {
        float qv = qs[c*QPAD + yy];
        accb += qv * inv2_s[yy];
#pragma unroll
        for (int ch = 0; ch < MID; ch++) a[ch] += qv * wi[ch*HW + yy];
    }
    float f2n = accb * (1.f/HW);
    // fold: h1[i][ch] = sum_c f1nbar[bi,c]*a[ch];  h2[i][ch] = sum_c w1p[bi,ch,c]*f2n
#pragma unroll
    for (int i = 0; i < WAY; i++) {
        float f1 = g_f1nbar[(size_t)(b*WAY + i)*C + c];
        const float* wp = g_w1p + (size_t)(b*WAY + i)*MID*C + c;
#pragma unroll
        for (int ch = 0; ch < MID; ch++) {
            float p0 = f1 * a[ch];
            float p1 = wp[(size_t)ch*C] * f2n;
#pragma unroll
            for (int o = 16; o; o >>= 1) {
                p0 += __shfl_down_sync(0xffffffffu, p0, o);
                p1 += __shfl_down_sync(0xffffffffu, p1, o);
            }
            if (lane == 0) {
                hred[w*64 + i*MID + ch]      = p0;
                hred[w*64 + 32 + i*MID + ch] = p1;
            }
        }
    }
    __syncthreads();
    if (t < 2*WAY*MID) {                                // 60 threads
        int path = t / (WAY*MID);
        int r = t % (WAY*MID);
        int off = path ? (32 + r) : r;
        float s = 0.f;
#pragma unroll
        for (int g = 0; g < 16; g++) s += hred[g*64 + off];
        int i = r / MID, ch = r % MID;
        float h = s + b1[ch];
        size_t idx = ((size_t)(b*WAY + i)*NQ + j)*MID + ch;
        if (path == 0) g_h1[idx] = h;
        else           g_h2[idx] = h;
    }
}

// ---------------- K4: deterministic BN stats ----------------
__global__ void k4_bn(const float* __restrict__ gamma, const float* __restrict__ beta) {
    int p = blockIdx.x / MID, ch = blockIdx.x % MID;
    const float* h = p ? g_h2 : g_h1;
    int t = threadIdx.x;                                // 256
    double s = 0.0, sq = 0.0;
    for (int n = t; n < BI*NQ; n += 256) {
        double v = (double)h[n*MID + ch];
        s += v; sq += v*v;
    }
    __shared__ double rs[256], rq[256];
    rs[t] = s; rq[t] = sq;
    __syncthreads();
    for (int o = 128; o; o >>= 1) {
        if (t < o) { rs[t] += rs[t+o]; rq[t] += rq[t+o]; }
        __syncthreads();
    }
    if (t == 0) {
        double mu  = rs[0] / 3000.0;
        double var = rq[0] / 3000.0 - mu*mu;
        float sd = sqrtf((float)var + 1e-5f);
        float sc = gamma[ch] / sd;
        g_bnscale[p*MID + ch] = sc;
        g_bnshift[p*MID + ch] = beta[ch] - (float)mu * sc;
    }
}

// ---------------- K5: fused attention + cls_scores + logits GEMM ----------------
__global__ __launch_bounds__(512, 2)
void k5_fused(const float* __restrict__ query, const float* __restrict__ qt,
              const float* __restrict__ w2, const float* __restrict__ b2,
              const float* __restrict__ clsw, const float* __restrict__ clsb,
              float* __restrict__ out_logits, float* __restrict__ out_cls) {
    extern __shared__ __align__(16) float sm[];
    float* qs     = sm;                  // [512][37]
    float* vu     = qs + C*QPAD;         // [5][512]: v1, later u; later ws alias
    float* pp     = vu + WAY*C;          // [5][512]
    float* inv1_s = pp + WAY*C;          // 180
    float* inv2_s = inv1_s + WAY*HW;     // 36
    float* w2_s   = inv2_s + HW;         // 216
    float* b2_s   = w2_s + MID*HW;       // 36
    float* scl    = b2_s + HW;           // 12
    float* shf    = scl + 2*MID;         // 12
    float* wv     = shf + 2*MID;         // 180
    float* coef2  = wv + WAY*HW;         // 180
    float* s_s    = coef2 + WAY*HW;      // 180
    float* att_s  = s_s + WAY*HW;        // 180
    float* red    = att_s + WAY*HW;      // 80
    float* pninv  = red + 80;            // 8
    float* asel   = pninv + 8;           // 36
    float* cb     = asel + HW;           // 64
    float* qt_s   = cb + NCLS;           // 8
    float* ws     = vu;                  // [64][68] alias (4352 <= 5120), used after pass4

    int bj = blockIdx.x; int b = bj / NQ, j = bj % NQ;
    int t = threadIdx.x;                                // 512
    int w = t >> 5, lane = t & 31;
    const float* q = query + (size_t)bj*C*HW;
    const float* pbase = g_protosT + (size_t)b*WAY*HW*C;

    for (int k = t; k < C*HW; k += 512) qs[(k/HW)*QPAD + k%HW] = q[k];
    if (t < WAY*HW) inv1_s[t] = g_inv1[b*WAY*HW + t];
    if (t < HW) inv2_s[t] = g_inv2[bj*HW + t];
    if (t < MID*HW) w2_s[t] = w2[t];
    if (t < HW) b2_s[t] = b2[t];
    if (t < 2*MID) { scl[t] = g_bnscale[t]; shf[t] = g_bnshift[t]; }
    if (t < NCLS) cb[t] = clsb[t];
    if (t < WAY) qt_s[t] = qt[bj*WAY + t];
    __syncthreads();

    // prologue: BN+relu+conv2 pre-activations -> wv (path1), coef2 (path2)
    if (t < WAY*HW) {
        int i = t / HW, y = t % HW;
        const float* h1p = g_h1 + ((size_t)(b*WAY+i)*NQ + j)*MID;
        const float* h2p = g_h2 + ((size_t)(b*WAY+i)*NQ + j)*MID;
        float a1 = b2_s[y], a2 = b2_s[y];
#pragma unroll
        for (int ch = 0; ch < MID; ch++) {
            float r1 = fmaxf(h1p[ch]*scl[ch]     + shf[ch],     0.f);
            float r2 = fmaxf(h2p[ch]*scl[MID+ch] + shf[MID+ch], 0.f);
            a1 += w2_s[y*MID + ch] * r1;
            a2 += w2_s[y*MID + ch] * r2;
        }
        wv[t]    = inv2_s[y] * a1 * (1.f/HW);
        coef2[t] = inv1_s[t] * a2 * (1.f/HW);
    }
    __syncthreads();

    // pass1: v1[i][c] from query (one c per thread)
    {
        int c = t;
        float a0=0.f,a1=0.f,a2=0.f,a3=0.f,a4=0.f;
#pragma unroll 4
        for (int y = 0; y < HW; y++) {
            float qv = qs[c*QPAD + y];
            a0 += qv*wv[0*HW+y]; a1 += qv*wv[1*HW+y]; a2 += qv*wv[2*HW+y];
            a3 += qv*wv[3*HW+y]; a4 += qv*wv[4*HW+y];
        }
        vu[0*C+c]=a0; vu[1*C+c]=a1; vu[2*C+c]=a2; vu[3*C+c]=a3; vu[4*C+c]=a4;
    }
    __syncthreads();

    // pass2: s1[i][x] = inv1 * p[i,x,:].v1 (warp per row)
    for (int r = w; r < WAY*HW; r += 16) {
        int i = r / HW, x = r % HW;
        const float* p = pbase + (size_t)(i*HW + x)*C;
        const float* v = vu + i*C;
        float s = 0.f;
        for (int c = lane; c < C; c += 32) s += p[c]*v[c];
#pragma unroll
        for (int o = 16; o; o >>= 1) s += __shfl_down_sync(0xffffffffu, s, o);
        if (lane == 0) s_s[r] = s * inv1_s[r];
    }
    __syncthreads();

    // softmax1 over x (+1): warp i -> row i
    if (w < WAY) {
        int i = w;
        float v0 = s_s[i*HW + lane];
        float v1v = (lane < HW-32) ? s_s[i*HW + 32 + lane] : -1e30f;
        float mx = fmaxf(v0, v1v);
#pragma unroll
        for (int o = 16; o; o >>= 1) mx = fmaxf(mx, __shfl_xor_sync(0xffffffffu, mx, o));
        float e0 = expf((v0 - mx) * 40.f);
        float e1 = (lane < HW-32) ? expf((v1v - mx) * 40.f) : 0.f;
        float sum = e0 + e1;
#pragma unroll
        for (int o = 16; o; o >>= 1) sum += __shfl_xor_sync(0xffffffffu, sum, o);
        float inv = 1.f / sum;
        att_s[i*HW + lane] = e0*inv + 1.f;
        if (lane < HW-32) att_s[i*HW + 32 + lane] = e1*inv + 1.f;
    }
    __syncthreads();

    // pass3: pp[i][c] (att1-pooled) and u[i][c] (coef2-pooled) in one protos read
    {
        int c = t;
        float sq[WAY];
#pragma unroll
        for (int i = 0; i < WAY; i++) {
            const float* p = pbase + (size_t)i*HW*C + c;
            float ap = 0.f, au = 0.f;
#pragma unroll 4
            for (int x = 0; x < HW; x++) {
                float pv = p[(size_t)x*C];
                ap += pv * att_s[i*HW + x];
                au += pv * coef2[i*HW + x];
            }
            ap *= (1.f/HW);
            pp[i*C + c] = ap;
            vu[i*C + c] = au;
            sq[i] = ap*ap;
        }
#pragma unroll
        for (int i = 0; i < WAY; i++) {
            float s = sq[i];
#pragma unroll
            for (int o = 16; o; o >>= 1) s += __shfl_down_sync(0xffffffffu, s, o);
            if (lane == 0) red[i*16 + w] = s;
        }
    }
    __syncthreads();
    if (t < WAY) {
        float s = 0.f;
#pragma unroll
        for (int g = 0; g < 16; g++) s += red[t*16 + g];
        pninv[t] = 1.f / fmaxf(sqrtf(s), 1e-12f);
    }
    __syncthreads();

    // pass4: cls_scores[i][y] and s2[i][y]
    for (int r = w; r < WAY*HW; r += 16) {
        int i = r / HW, y = r % HW;
        float d1 = 0.f, d2 = 0.f;
        for (int c = lane; c < C; c += 32) {
            float qv = qs[c*QPAD + y];
            d1 += qv * pp[i*C + c];
            d2 += qv * vu[i*C + c];
        }
#pragma unroll
        for (int o = 16; o; o >>= 1) {
            d1 += __shfl_down_sync(0xffffffffu, d1, o);
            d2 += __shfl_down_sync(0xffffffffu, d2, o);
        }
        if (lane == 0) {
            out_cls[((size_t)bj*WAY + i)*HW + y] = 7.f * pninv[i] * inv2_s[y] * d1;
            s_s[r] = inv2_s[y] * d2;
        }
    }
    __syncthreads();

    // softmax2 over y (+1) -> att_s (att2)
    if (w < WAY) {
        int i = w;
        float v0 = s_s[i*HW + lane];
        float v1v = (lane < HW-32) ? s_s[i*HW + 32 + lane] : -1e30f;
        float mx = fmaxf(v0, v1v);
#pragma unroll
        for (int o = 16; o; o >>= 1) mx = fmaxf(mx, __shfl_xor_sync(0xffffffffu, mx, o));
        float e0 = expf((v0 - mx) * 40.f);
        float e1 = (lane < HW-32) ? expf((v1v - mx) * 40.f) : 0.f;
        float sum = e0 + e1;
#pragma unroll
        for (int o = 16; o; o >>= 1) sum += __shfl_xor_sync(0xffffffffu, sum, o);
        float inv = 1.f / sum;
        att_s[i*HW + lane] = e0*inv + 1.f;
        if (lane < HW-32) att_s[i*HW + 32 + lane] = e1*inv + 1.f;
    }
    __syncthreads();

    // asel[y] = sum_i qt[i] * att2[i][y]
    if (t < HW) {
        float a = 0.f;
#pragma unroll
        for (int i = 0; i < WAY; i++) a += qt_s[i] * att_s[i*HW + t];
        asel[t] = a;
    }

    // logits GEMM: out[o][y] = asel[y] * sum_c clsw[o][c]*q[c][y] + cb[o]
    int og = t & 15, yg = t >> 4;                       // valid for t < 144
    int o0 = og*4, y0 = yg*4;
    unsigned long long acc2[8];
#pragma unroll
    for (int k = 0; k < 8; k++) acc2[k] = 0ull;

    for (int c0 = 0; c0 < C; c0 += 64) {
        __syncthreads();                                // protect ws (aliases vu/pp)
        for (int k = t; k < 64*64; k += 512) {
            int c = k & 63, o = k >> 6;
            ws[c*68 + o] = clsw[o*C + c0 + c];
        }
        __syncthreads();
        if (t < 144) {
#pragma unroll 4
            for (int cc = 0; cc < 64; cc++) {
                const float* qrow = qs + (c0 + cc)*QPAD + y0;
                unsigned long long qb0 = pack2(qrow[0], qrow[0]);
                unsigned long long qb1 = pack2(qrow[1], qrow[1]);
                unsigned long long qb2 = pack2(qrow[2], qrow[2]);
                unsigned long long qb3 = pack2(qrow[3], qrow[3]);
                unsigned long long w01 = *(const unsigned long long*)&ws[cc*68 + o0];
                unsigned long long w23 = *(const unsigned long long*)&ws[cc*68 + o0 + 2];
                fma2(acc2[0], w01, qb0); fma2(acc2[1], w01, qb1);
                fma2(acc2[2], w01, qb2); fma2(acc2[3], w01, qb3);
                fma2(acc2[4], w23, qb0); fma2(acc2[5], w23, qb1);
                fma2(acc2[6], w23, qb2); fma2(acc2[7], w23, qb3);
            }
        }
    }
    if (t < 144) {
        float* op = out_logits + (size_t)bj*NCLS*HW;
#pragma unroll
        for (int p = 0; p < 2; p++) {
#pragma unroll
            for (int y = 0; y < 4; y++) {
                float lo, hi;
                unpack2(acc2[p*4 + y], lo, hi);
                float a = asel[y0 + y];
                op[(o0 + 2*p    )*HW + y0 + y] = a*lo + cb[o0 + 2*p];
                op[(o0 + 2*p + 1)*HW + y0 + y] = a*hi + cb[o0 + 2*p + 1];
            }
        }
    }
}
#define K5F_SMEM ((C*QPAD + 2*WAY*C + 6*WAY*HW + 2*HW + MID*HW + 4*MID + 88 + HW + NCLS + 8)*4 + 64)

// ---------------- launch ----------------
extern "C" void kernel_launch(void* const* d_in, const int* in_sizes, int n_in,
                              void* d_out, int out_size) {
    const float* sup   = (const float*)d_in[0];
    const float* query = (const float*)d_in[1];
    const float* st    = (const float*)d_in[2];
    const float* qt    = (const float*)d_in[3];
    const float* w1    = (const float*)d_in[4];
    const float* b1    = (const float*)d_in[5];
    const float* gamma = (const float*)d_in[6];
    const float* beta  = (const float*)d_in[7];
    const float* w2    = (const float*)d_in[8];
    const float* b2    = (const float*)d_in[9];
    const float* clsw  = (const float*)d_in[10];
    const float* clsb  = (const float*)d_in[11];
    float* out = (float*)d_out;

    cudaFuncSetAttribute(k5_fused, cudaFuncAttributeMaxDynamicSharedMemorySize, K5F_SMEM);
    cudaFuncSetAttribute(k2_qnorms, cudaFuncAttributeMaxDynamicSharedMemorySize, C*QPAD*4);

    k1_protos<<<dim3(72, B), 256>>>(sup, st);
    k1b_norms<<<BI, 512>>>(w1);
    k2_qnorms<<<BJ, 512, C*QPAD*4>>>(query, w1, b1);
    k4_bn<<<2*MID, 256>>>(gamma, beta);
    k5_fused<<<BJ, 512, K5F_SMEM>>>(query, qt, w2, b2, clsw, clsb,
                                    out, out + LOGITS_N);
}